// round 3
// baseline (speedup 1.0000x reference)
#include <cuda_runtime.h>
#include <math.h>

#define DD 1024
#define HH 16
#define HDIM 64
#define TT 2048
#define BB 2
#define MR 4096            // B*T
#define THRESHF 0.29514f
#define SHARPF 15.0f

// -------------------- scratch (device globals; no allocation) --------------------
__device__ float g_xn[(size_t)MR * DD];
__device__ float g_q [(size_t)MR * DD];
__device__ float g_k [(size_t)MR * DD];
__device__ float g_v [(size_t)MR * DD];
__device__ float g_col[(size_t)MR * DD];
__device__ float g_gq[MR * HH];
__device__ float g_gk[MR * HH];

// -------------------- LayerNorm: one block per row --------------------
__global__ __launch_bounds__(256) void ln_kernel(const float* __restrict__ x,
                                                 const float* __restrict__ w,
                                                 const float* __restrict__ bia,
                                                 float* __restrict__ y) {
    int row = blockIdx.x;
    const float4* xr = (const float4*)(x + (size_t)row * DD);
    float4 v = xr[threadIdx.x];
    float sum = v.x + v.y + v.z + v.w;
    float sq  = v.x*v.x + v.y*v.y + v.z*v.z + v.w*v.w;
#pragma unroll
    for (int o = 16; o > 0; o >>= 1) {
        sum += __shfl_xor_sync(0xffffffffu, sum, o);
        sq  += __shfl_xor_sync(0xffffffffu, sq, o);
    }
    __shared__ float s1[8], s2[8];
    int wid = threadIdx.x >> 5;
    if ((threadIdx.x & 31) == 0) { s1[wid] = sum; s2[wid] = sq; }
    __syncthreads();
    sum = 0.f; sq = 0.f;
#pragma unroll
    for (int i = 0; i < 8; i++) { sum += s1[i]; sq += s2[i]; }
    float mean = sum * (1.0f / DD);
    float var  = sq * (1.0f / DD) - mean * mean;
    float inv  = rsqrtf(var + 1e-5f);
    float4 wv = ((const float4*)w)[threadIdx.x];
    float4 bv = ((const float4*)bia)[threadIdx.x];
    float4 o;
    o.x = (v.x - mean) * inv * wv.x + bv.x;
    o.y = (v.y - mean) * inv * wv.y + bv.y;
    o.z = (v.z - mean) * inv * wv.z + bv.z;
    o.w = (v.w - mean) * inv * wv.w + bv.w;
    ((float4*)(y + (size_t)row * DD))[threadIdx.x] = o;
}

// -------------------- SGEMM: C[M,N] = A[M,K] * W[K,N] (+bias), K=N=1024 --------------------
// 64x64 block tile, BK=16, 256 threads, 4x4 per-thread microtile.
__global__ __launch_bounds__(256) void sgemm_kernel(const float* __restrict__ A,
                                                    const float* __restrict__ W,
                                                    const float* __restrict__ bias,
                                                    float* __restrict__ C) {
    __shared__ float As[16][64];   // [k][m] (transposed store)
    __shared__ float Ws[16][64];   // [k][n]
    int tid = threadIdx.x;
    int tx = tid & 15, ty = tid >> 4;
    int m0 = blockIdx.y << 6, n0 = blockIdx.x << 6;

    int a_row = tid >> 2;            // 0..63
    int a_col = (tid & 3) << 2;      // 0,4,8,12
    int w_row = tid >> 4;            // 0..15
    int w_col = (tid & 15) << 2;     // 0..60

    const float* Ap = A + (size_t)(m0 + a_row) * DD + a_col;
    const float* Wp = W + (size_t)w_row * DD + n0 + w_col;

    float acc[4][4] = {};
    for (int k0 = 0; k0 < DD; k0 += 16) {
        float4 av = *(const float4*)(Ap + k0);
        float4 wv = *(const float4*)(Wp + (size_t)k0 * DD);
        __syncthreads();
        As[a_col + 0][a_row] = av.x;
        As[a_col + 1][a_row] = av.y;
        As[a_col + 2][a_row] = av.z;
        As[a_col + 3][a_row] = av.w;
        *(float4*)&Ws[w_row][w_col] = wv;
        __syncthreads();
#pragma unroll
        for (int kk = 0; kk < 16; kk++) {
            float4 a4 = *(const float4*)&As[kk][ty << 2];
            float4 b4 = *(const float4*)&Ws[kk][tx << 2];
            float a[4]  = {a4.x, a4.y, a4.z, a4.w};
            float bb[4] = {b4.x, b4.y, b4.z, b4.w};
#pragma unroll
            for (int i = 0; i < 4; i++)
#pragma unroll
                for (int j = 0; j < 4; j++) acc[i][j] += a[i] * bb[j];
        }
    }
    float4 badd = make_float4(0.f, 0.f, 0.f, 0.f);
    if (bias) badd = *(const float4*)&bias[n0 + (tx << 2)];
#pragma unroll
    for (int i = 0; i < 4; i++) {
        float4 o = make_float4(acc[i][0] + badd.x, acc[i][1] + badd.y,
                               acc[i][2] + badd.z, acc[i][3] + badd.w);
        *(float4*)&C[(size_t)(m0 + (ty << 2) + i) * DD + n0 + (tx << 2)] = o;
    }
}

// -------------------- L2 normalize q,k (64-elem heads) + gates; warp per (b,t,h) ----------
__global__ __launch_bounds__(256) void qknorm_kernel(float* __restrict__ q,
                                                     float* __restrict__ k,
                                                     const float* __restrict__ gqw,
                                                     const float* __restrict__ gkw,
                                                     float* __restrict__ gateq,
                                                     float* __restrict__ gatek) {
    int r = blockIdx.x * 8 + (threadIdx.x >> 5);   // flat (b*T+t)*H + h
    int lane = threadIdx.x & 31;
    size_t base = (size_t)r * HDIM + lane * 2;

    float2 g1 = *(const float2*)&gqw[lane * 2];
    float2 g2 = *(const float2*)&gkw[lane * 2];

    // q
    float2 qv = *(float2*)&q[base];
    float ss = qv.x * qv.x + qv.y * qv.y;
#pragma unroll
    for (int o = 16; o > 0; o >>= 1) ss += __shfl_xor_sync(0xffffffffu, ss, o);
    float inv = 1.0f / fmaxf(sqrtf(ss), 1e-12f);
    qv.x *= inv; qv.y *= inv;
    *(float2*)&q[base] = qv;
    float gd = qv.x * g1.x + qv.y * g1.y;
#pragma unroll
    for (int o = 16; o > 0; o >>= 1) gd += __shfl_xor_sync(0xffffffffu, gd, o);
    if (lane == 0) gateq[r] = gd;

    // k
    float2 kv = *(float2*)&k[base];
    ss = kv.x * kv.x + kv.y * kv.y;
#pragma unroll
    for (int o = 16; o > 0; o >>= 1) ss += __shfl_xor_sync(0xffffffffu, ss, o);
    inv = 1.0f / fmaxf(sqrtf(ss), 1e-12f);
    kv.x *= inv; kv.y *= inv;
    *(float2*)&k[base] = kv;
    gd = kv.x * g2.x + kv.y * g2.y;
#pragma unroll
    for (int o = 16; o > 0; o >>= 1) gd += __shfl_xor_sync(0xffffffffu, gd, o);
    if (lane == 0) gatek[r] = gd;
}

// -------------------- fused attention: per (b,h,t-tile of 64) --------------------
// collapse[t,:] = sum_s sigmoid((q_t.k_s - TH)*SHARP) * gq_t * gk_s * v_s
#define TSTRIDE 68
__global__ __launch_bounds__(256) void attn_kernel(const float* __restrict__ q,
                                                   const float* __restrict__ k,
                                                   const float* __restrict__ v,
                                                   const float* __restrict__ gateq,
                                                   const float* __restrict__ gatek,
                                                   float* __restrict__ outc) {
    extern __shared__ float sm[];
    float* Qt  = sm;                       // [64(d)][68]  d-major (transposed)
    float* Kt  = sm + 64 * TSTRIDE;        // [64(d)][68]  d-major
    float* Vs  = sm + 2 * 64 * TSTRIDE;    // [64(s)][68]  row-major
    float* Ps  = sm + 3 * 64 * TSTRIDE;    // [64(j)][68]  j-major (transposed P)
    float* gqs = sm + 4 * 64 * TSTRIDE;    // 64
    float* gks = gqs + 64;                 // 64

    int tid = threadIdx.x;
    int tx = tid & 15, ty = tid >> 4;
    int t0 = blockIdx.x << 6;
    int h = blockIdx.y, b = blockIdx.z;
    size_t headoff = (size_t)b * TT * DD + (size_t)h * HDIM;

    // load Q tile transposed (d-major)
    for (int u = tid; u < 1024; u += 256) {
        int r = u >> 4, c = (u & 15) << 2;
        float4 qv = *(const float4*)&q[headoff + (size_t)(t0 + r) * DD + c];
        Qt[(c + 0) * TSTRIDE + r] = qv.x;
        Qt[(c + 1) * TSTRIDE + r] = qv.y;
        Qt[(c + 2) * TSTRIDE + r] = qv.z;
        Qt[(c + 3) * TSTRIDE + r] = qv.w;
    }
    if (tid < 64) gqs[tid] = gateq[(size_t)(b * TT + t0 + tid) * HH + h];

    float acc[4][4] = {};
    for (int s0 = 0; s0 < TT; s0 += 64) {
        __syncthreads();   // protects Kt/Vs/Ps/gks from previous iteration's readers
        for (int u = tid; u < 1024; u += 256) {
            int r = u >> 4, c = (u & 15) << 2;
            size_t ga = headoff + (size_t)(s0 + r) * DD + c;
            float4 kv = *(const float4*)&k[ga];
            Kt[(c + 0) * TSTRIDE + r] = kv.x;
            Kt[(c + 1) * TSTRIDE + r] = kv.y;
            Kt[(c + 2) * TSTRIDE + r] = kv.z;
            Kt[(c + 3) * TSTRIDE + r] = kv.w;
            float4 vv = *(const float4*)&v[ga];
            *(float4*)&Vs[r * TSTRIDE + c] = vv;
        }
        if (tid < 64) gks[tid] = gatek[(size_t)(b * TT + s0 + tid) * HH + h];
        __syncthreads();

        // S = Q K^T  (4x4 per thread; rows ty*4+i, cols tx*4+j)
        float s[4][4] = {};
#pragma unroll 8
        for (int d = 0; d < 64; d++) {
            float4 a4 = *(const float4*)&Qt[d * TSTRIDE + (ty << 2)];
            float4 b4 = *(const float4*)&Kt[d * TSTRIDE + (tx << 2)];
            float a[4]  = {a4.x, a4.y, a4.z, a4.w};
            float bb[4] = {b4.x, b4.y, b4.z, b4.w};
#pragma unroll
            for (int i = 0; i < 4; i++)
#pragma unroll
                for (int j = 0; j < 4; j++) s[i][j] += a[i] * bb[j];
        }

        // modulation -> Ps (stored j-major so PV can read float4 over i)
        float4 gq4 = *(const float4*)&gqs[ty << 2];
        float4 gk4 = *(const float4*)&gks[tx << 2];
        float gqa[4] = {gq4.x, gq4.y, gq4.z, gq4.w};
        float gka[4] = {gk4.x, gk4.y, gk4.z, gk4.w};
#pragma unroll
        for (int j = 0; j < 4; j++) {
            float pc[4];
#pragma unroll
            for (int i = 0; i < 4; i++) {
                float z = (s[i][j] - THRESHF) * SHARPF;
                float sg = __fdividef(1.0f, 1.0f + __expf(-z));
                pc[i] = sg * gqa[i] * gka[j];
            }
            *(float4*)&Ps[((tx << 2) + j) * TSTRIDE + (ty << 2)] =
                make_float4(pc[0], pc[1], pc[2], pc[3]);
        }
        __syncthreads();

        // acc += P @ V  (rows ty*4+i, cols tx*4+c)
#pragma unroll 8
        for (int j = 0; j < 64; j++) {
            float4 p4 = *(const float4*)&Ps[j * TSTRIDE + (ty << 2)];
            float4 v4 = *(const float4*)&Vs[j * TSTRIDE + (tx << 2)];
            float pa[4] = {p4.x, p4.y, p4.z, p4.w};
            float va[4] = {v4.x, v4.y, v4.z, v4.w};
#pragma unroll
            for (int i = 0; i < 4; i++)
#pragma unroll
                for (int c = 0; c < 4; c++) acc[i][c] += pa[i] * va[c];
        }
    }

#pragma unroll
    for (int i = 0; i < 4; i++) {
        float4 o = make_float4(acc[i][0], acc[i][1], acc[i][2], acc[i][3]);
        *(float4*)&outc[headoff + (size_t)(t0 + (ty << 2) + i) * DD + (tx << 2)] = o;
    }
}

// -------------------- launch --------------------
extern "C" void kernel_launch(void* const* d_in, const int* in_sizes, int n_in,
                              void* d_out, int out_size) {
    (void)in_sizes; (void)n_in; (void)out_size;
    const float* x   = (const float*)d_in[0];
    const float* Wq  = (const float*)d_in[1];
    const float* Wk  = (const float*)d_in[2];
    const float* Wv  = (const float*)d_in[3];
    const float* gq  = (const float*)d_in[4];
    const float* gk  = (const float*)d_in[5];
    const float* Wo  = (const float*)d_in[6];
    const float* bo  = (const float*)d_in[7];
    const float* lnw = (const float*)d_in[8];
    const float* lnb = (const float*)d_in[9];
    float* out = (float*)d_out;

    float *xn, *qb, *kb, *vb, *col, *gqv, *gkv;
    cudaGetSymbolAddress((void**)&xn,  g_xn);
    cudaGetSymbolAddress((void**)&qb,  g_q);
    cudaGetSymbolAddress((void**)&kb,  g_k);
    cudaGetSymbolAddress((void**)&vb,  g_v);
    cudaGetSymbolAddress((void**)&col, g_col);
    cudaGetSymbolAddress((void**)&gqv, g_gq);
    cudaGetSymbolAddress((void**)&gkv, g_gk);

    const int smem_bytes = (4 * 64 * TSTRIDE + 128) * (int)sizeof(float);  // 70144
    cudaFuncSetAttribute(attn_kernel, cudaFuncAttributeMaxDynamicSharedMemorySize,
                         smem_bytes);

    dim3 gemm_grid(DD / 64, MR / 64);   // (16, 64)

    ln_kernel<<<MR, 256>>>(x, lnw, lnb, xn);
    sgemm_kernel<<<gemm_grid, 256>>>(xn, Wq, nullptr, qb);
    sgemm_kernel<<<gemm_grid, 256>>>(xn, Wk, nullptr, kb);
    sgemm_kernel<<<gemm_grid, 256>>>(x,  Wv, nullptr, vb);
    qknorm_kernel<<<(MR * HH) / 8, 256>>>(qb, kb, gq, gk, gqv, gkv);
    attn_kernel<<<dim3(TT / 64, HH, BB), 256, smem_bytes>>>(qb, kb, vb, gqv, gkv, col);
    sgemm_kernel<<<gemm_grid, 256>>>(col, Wo, bo, out);
}

// round 4
// speedup vs baseline: 1.1936x; 1.1936x over previous
#include <cuda_runtime.h>
#include <math.h>

#define DD 1024
#define HH 16
#define HDIM 64
#define TT 2048
#define BB 2
#define MR 4096            // B*T
#define THRESHF 0.29514f
#define SHARPF 15.0f

// -------------------- scratch (device globals; no allocation) --------------------
__device__ float g_xn[(size_t)MR * DD];
__device__ float g_q [(size_t)MR * DD];
__device__ float g_k [(size_t)MR * DD];
__device__ float g_v [(size_t)MR * DD];
__device__ float g_col[(size_t)MR * DD];
__device__ float g_gq[MR * HH];
__device__ float g_gk[MR * HH];

// -------------------- LayerNorm: one block per row --------------------
__global__ __launch_bounds__(256) void ln_kernel(const float* __restrict__ x,
                                                 const float* __restrict__ w,
                                                 const float* __restrict__ bia,
                                                 float* __restrict__ y) {
    int row = blockIdx.x;
    const float4* xr = (const float4*)(x + (size_t)row * DD);
    float4 v = xr[threadIdx.x];
    float sum = v.x + v.y + v.z + v.w;
    float sq  = v.x*v.x + v.y*v.y + v.z*v.z + v.w*v.w;
#pragma unroll
    for (int o = 16; o > 0; o >>= 1) {
        sum += __shfl_xor_sync(0xffffffffu, sum, o);
        sq  += __shfl_xor_sync(0xffffffffu, sq, o);
    }
    __shared__ float s1[8], s2[8];
    int wid = threadIdx.x >> 5;
    if ((threadIdx.x & 31) == 0) { s1[wid] = sum; s2[wid] = sq; }
    __syncthreads();
    sum = 0.f; sq = 0.f;
#pragma unroll
    for (int i = 0; i < 8; i++) { sum += s1[i]; sq += s2[i]; }
    float mean = sum * (1.0f / DD);
    float var  = sq * (1.0f / DD) - mean * mean;
    float inv  = rsqrtf(var + 1e-5f);
    float4 wv = ((const float4*)w)[threadIdx.x];
    float4 bv = ((const float4*)bia)[threadIdx.x];
    float4 o;
    o.x = (v.x - mean) * inv * wv.x + bv.x;
    o.y = (v.y - mean) * inv * wv.y + bv.y;
    o.z = (v.z - mean) * inv * wv.z + bv.z;
    o.w = (v.w - mean) * inv * wv.w + bv.w;
    ((float4*)(y + (size_t)row * DD))[threadIdx.x] = o;
}

// -------------------- SGEMM: C[M,N] = A[M,K] * W[K,N] (+bias) --------------------
// 128x128 block tile, BK=16, 256 threads, 8x8 microtile (4+4 quadrant split).
__global__ __launch_bounds__(256, 2) void sgemm_kernel(const float* __restrict__ A,
                                                       const float* __restrict__ W,
                                                       const float* __restrict__ bias,
                                                       float* __restrict__ C) {
    __shared__ float As[16][128];   // [k][m] transposed
    __shared__ float Bs[16][128];   // [k][n]
    int tid = threadIdx.x;
    int tx = tid & 15, ty = tid >> 4;
    int m0 = blockIdx.y << 7, n0 = blockIdx.x << 7;

    int ar = tid >> 1;               // 0..127
    int ac = (tid & 1) << 3;         // 0 or 8
    int br = tid >> 4;               // 0..15
    int bc = (tid & 15) << 3;        // 0..120

    const float* Ap = A + (size_t)(m0 + ar) * DD + ac;
    const float* Wp = W + (size_t)br * DD + n0 + bc;

    float acc[8][8] = {};

    float4 av0 = *(const float4*)(Ap);
    float4 av1 = *(const float4*)(Ap + 4);
    float4 bv0 = *(const float4*)(Wp);
    float4 bv1 = *(const float4*)(Wp + 4);

    for (int k0 = 0; k0 < DD; k0 += 16) {
        __syncthreads();
        As[ac + 0][ar] = av0.x;
        As[ac + 1][ar] = av0.y;
        As[ac + 2][ar] = av0.z;
        As[ac + 3][ar] = av0.w;
        As[ac + 4][ar] = av1.x;
        As[ac + 5][ar] = av1.y;
        As[ac + 6][ar] = av1.z;
        As[ac + 7][ar] = av1.w;
        *(float4*)&Bs[br][bc]     = bv0;
        *(float4*)&Bs[br][bc + 4] = bv1;
        __syncthreads();

        if (k0 + 16 < DD) {
            av0 = *(const float4*)(Ap + k0 + 16);
            av1 = *(const float4*)(Ap + k0 + 20);
            bv0 = *(const float4*)(Wp + (size_t)(k0 + 16) * DD);
            bv1 = *(const float4*)(Wp + (size_t)(k0 + 16) * DD + 4);
        }

#pragma unroll
        for (int kk = 0; kk < 16; kk++) {
            float a[8], b[8];
            *(float4*)&a[0] = *(const float4*)&As[kk][ty << 2];
            *(float4*)&a[4] = *(const float4*)&As[kk][64 + (ty << 2)];
            *(float4*)&b[0] = *(const float4*)&Bs[kk][tx << 2];
            *(float4*)&b[4] = *(const float4*)&Bs[kk][64 + (tx << 2)];
#pragma unroll
            for (int i = 0; i < 8; i++)
#pragma unroll
                for (int j = 0; j < 8; j++) acc[i][j] += a[i] * b[j];
        }
    }

    float4 bad0 = make_float4(0.f, 0.f, 0.f, 0.f);
    float4 bad1 = bad0;
    if (bias) {
        bad0 = *(const float4*)&bias[n0 + (tx << 2)];
        bad1 = *(const float4*)&bias[n0 + 64 + (tx << 2)];
    }
#pragma unroll
    for (int qi = 0; qi < 2; qi++) {
#pragma unroll
        for (int i = 0; i < 4; i++) {
            int row = m0 + qi * 64 + (ty << 2) + i;
            int ii = qi * 4 + i;
            float4 o0 = make_float4(acc[ii][0] + bad0.x, acc[ii][1] + bad0.y,
                                    acc[ii][2] + bad0.z, acc[ii][3] + bad0.w);
            float4 o1 = make_float4(acc[ii][4] + bad1.x, acc[ii][5] + bad1.y,
                                    acc[ii][6] + bad1.z, acc[ii][7] + bad1.w);
            *(float4*)&C[(size_t)row * DD + n0 + (tx << 2)]      = o0;
            *(float4*)&C[(size_t)row * DD + n0 + 64 + (tx << 2)] = o1;
        }
    }
}

// -------------------- L2 normalize q,k (64-elem heads) + gates; warp per (b,t,h) ----------
__global__ __launch_bounds__(256) void qknorm_kernel(float* __restrict__ q,
                                                     float* __restrict__ k,
                                                     const float* __restrict__ gqw,
                                                     const float* __restrict__ gkw,
                                                     float* __restrict__ gateq,
                                                     float* __restrict__ gatek) {
    int r = blockIdx.x * 8 + (threadIdx.x >> 5);   // flat (b*T+t)*H + h
    int lane = threadIdx.x & 31;
    size_t base = (size_t)r * HDIM + lane * 2;

    float2 g1 = *(const float2*)&gqw[lane * 2];
    float2 g2 = *(const float2*)&gkw[lane * 2];

    float2 qv = *(float2*)&q[base];
    float ss = qv.x * qv.x + qv.y * qv.y;
#pragma unroll
    for (int o = 16; o > 0; o >>= 1) ss += __shfl_xor_sync(0xffffffffu, ss, o);
    float inv = 1.0f / fmaxf(sqrtf(ss), 1e-12f);
    qv.x *= inv; qv.y *= inv;
    *(float2*)&q[base] = qv;
    float gd = qv.x * g1.x + qv.y * g1.y;
#pragma unroll
    for (int o = 16; o > 0; o >>= 1) gd += __shfl_xor_sync(0xffffffffu, gd, o);
    if (lane == 0) gateq[r] = gd;

    float2 kv = *(float2*)&k[base];
    ss = kv.x * kv.x + kv.y * kv.y;
#pragma unroll
    for (int o = 16; o > 0; o >>= 1) ss += __shfl_xor_sync(0xffffffffu, ss, o);
    inv = 1.0f / fmaxf(sqrtf(ss), 1e-12f);
    kv.x *= inv; kv.y *= inv;
    *(float2*)&k[base] = kv;
    gd = kv.x * g2.x + kv.y * g2.y;
#pragma unroll
    for (int o = 16; o > 0; o >>= 1) gd += __shfl_xor_sync(0xffffffffu, gd, o);
    if (lane == 0) gatek[r] = gd;
}

// -------------------- fused attention: 128(t) x 64(s) tiles, 8x4 microtile --------------
#define TSQ 132    // stride for 128-wide t-major rows (Qt, Ps)
#define TSK 68     // stride for 64-wide rows (Kt, Vs)
__global__ __launch_bounds__(256, 2) void attn_kernel(const float* __restrict__ q,
                                                      const float* __restrict__ k,
                                                      const float* __restrict__ v,
                                                      const float* __restrict__ gateq,
                                                      const float* __restrict__ gatek,
                                                      float* __restrict__ outc) {
    extern __shared__ float sm[];
    float* Qt  = sm;                        // [64 d][TSQ]  d-major (t cols)
    float* Ps  = Qt + 64 * TSQ;             // [64 s][TSQ]  t-major
    float* Kt  = Ps + 64 * TSQ;             // [64 d][TSK]  d-major (s cols)
    float* Vs  = Kt + 64 * TSK;             // [64 s][TSK]  row-major (d cols)
    float* gqs = Vs + 64 * TSK;             // [128]
    float* gks = gqs + 128;                 // [64]

    int tid = threadIdx.x;
    int tx = tid & 15, ty = tid >> 4;       // tx: s/d cols (4), ty: t rows (4+4)
    int t0 = blockIdx.x << 7;
    int h = blockIdx.y, b = blockIdx.z;
    size_t headoff = (size_t)b * TT * DD + (size_t)h * HDIM;

    // load Q tile transposed (d-major): 128 rows x 64 d
    for (int u = tid; u < 128 * 16; u += 256) {
        int r = u >> 4, c = (u & 15) << 2;
        float4 qv = *(const float4*)&q[headoff + (size_t)(t0 + r) * DD + c];
        Qt[(c + 0) * TSQ + r] = qv.x;
        Qt[(c + 1) * TSQ + r] = qv.y;
        Qt[(c + 2) * TSQ + r] = qv.z;
        Qt[(c + 3) * TSQ + r] = qv.w;
    }
    if (tid < 128) gqs[tid] = gateq[(size_t)(b * TT + t0 + tid) * HH + h];

    float acc0[4][4] = {};   // t rows ty*4+i, d cols tx*4+c
    float acc1[4][4] = {};   // t rows 64+ty*4+i

    for (int s0 = 0; s0 < TT; s0 += 64) {
        __syncthreads();   // prev PV done reading Vs/Ps
        for (int u = tid; u < 64 * 16; u += 256) {
            int r = u >> 4, c = (u & 15) << 2;
            size_t ga = headoff + (size_t)(s0 + r) * DD + c;
            float4 kv = *(const float4*)&k[ga];
            Kt[(c + 0) * TSK + r] = kv.x;
            Kt[(c + 1) * TSK + r] = kv.y;
            Kt[(c + 2) * TSK + r] = kv.z;
            Kt[(c + 3) * TSK + r] = kv.w;
            float4 vv = *(const float4*)&v[ga];
            *(float4*)&Vs[r * TSK + c] = vv;
        }
        if (tid < 64) gks[tid] = gatek[(size_t)(b * TT + s0 + tid) * HH + h];
        __syncthreads();

        // S = Q K^T : rows (ty*4+i, 64+ty*4+i), cols tx*4+j
        float s0r[4][4] = {}, s1r[4][4] = {};
#pragma unroll 8
        for (int d = 0; d < 64; d++) {
            float a0[4], a1[4], bb[4];
            *(float4*)&a0[0] = *(const float4*)&Qt[d * TSQ + (ty << 2)];
            *(float4*)&a1[0] = *(const float4*)&Qt[d * TSQ + 64 + (ty << 2)];
            *(float4*)&bb[0] = *(const float4*)&Kt[d * TSK + (tx << 2)];
#pragma unroll
            for (int i = 0; i < 4; i++)
#pragma unroll
                for (int j = 0; j < 4; j++) {
                    s0r[i][j] += a0[i] * bb[j];
                    s1r[i][j] += a1[i] * bb[j];
                }
        }

        // modulation -> Ps (t-major rows per s)
        float gq0[4], gq1[4], gk4[4];
        *(float4*)&gq0[0] = *(const float4*)&gqs[ty << 2];
        *(float4*)&gq1[0] = *(const float4*)&gqs[64 + (ty << 2)];
        *(float4*)&gk4[0] = *(const float4*)&gks[tx << 2];
#pragma unroll
        for (int j = 0; j < 4; j++) {
            float p0[4], p1[4];
#pragma unroll
            for (int i = 0; i < 4; i++) {
                float z0 = (s0r[i][j] - THRESHF) * SHARPF;
                float sg0 = __fdividef(1.0f, 1.0f + __expf(-z0));
                p0[i] = sg0 * gq0[i] * gk4[j];
                float z1 = (s1r[i][j] - THRESHF) * SHARPF;
                float sg1 = __fdividef(1.0f, 1.0f + __expf(-z1));
                p1[i] = sg1 * gq1[i] * gk4[j];
            }
            *(float4*)&Ps[((tx << 2) + j) * TSQ + (ty << 2)] =
                make_float4(p0[0], p0[1], p0[2], p0[3]);
            *(float4*)&Ps[((tx << 2) + j) * TSQ + 64 + (ty << 2)] =
                make_float4(p1[0], p1[1], p1[2], p1[3]);
        }
        __syncthreads();

        // acc += P @ V : rows t quadrants, cols d = tx*4
#pragma unroll 8
        for (int s = 0; s < 64; s++) {
            float p0[4], p1[4], vv[4];
            *(float4*)&p0[0] = *(const float4*)&Ps[s * TSQ + (ty << 2)];
            *(float4*)&p1[0] = *(const float4*)&Ps[s * TSQ + 64 + (ty << 2)];
            *(float4*)&vv[0] = *(const float4*)&Vs[s * TSK + (tx << 2)];
#pragma unroll
            for (int i = 0; i < 4; i++)
#pragma unroll
                for (int c = 0; c < 4; c++) {
                    acc0[i][c] += p0[i] * vv[c];
                    acc1[i][c] += p1[i] * vv[c];
                }
        }
    }

#pragma unroll
    for (int i = 0; i < 4; i++) {
        float4 o0 = make_float4(acc0[i][0], acc0[i][1], acc0[i][2], acc0[i][3]);
        *(float4*)&outc[headoff + (size_t)(t0 + (ty << 2) + i) * DD + (tx << 2)] = o0;
        float4 o1 = make_float4(acc1[i][0], acc1[i][1], acc1[i][2], acc1[i][3]);
        *(float4*)&outc[headoff + (size_t)(t0 + 64 + (ty << 2) + i) * DD + (tx << 2)] = o1;
    }
}

// -------------------- launch --------------------
extern "C" void kernel_launch(void* const* d_in, const int* in_sizes, int n_in,
                              void* d_out, int out_size) {
    (void)in_sizes; (void)n_in; (void)out_size;
    const float* x   = (const float*)d_in[0];
    const float* Wq  = (const float*)d_in[1];
    const float* Wk  = (const float*)d_in[2];
    const float* Wv  = (const float*)d_in[3];
    const float* gq  = (const float*)d_in[4];
    const float* gk  = (const float*)d_in[5];
    const float* Wo  = (const float*)d_in[6];
    const float* bo  = (const float*)d_in[7];
    const float* lnw = (const float*)d_in[8];
    const float* lnb = (const float*)d_in[9];
    float* out = (float*)d_out;

    float *xn, *qb, *kb, *vb, *col, *gqv, *gkv;
    cudaGetSymbolAddress((void**)&xn,  g_xn);
    cudaGetSymbolAddress((void**)&qb,  g_q);
    cudaGetSymbolAddress((void**)&kb,  g_k);
    cudaGetSymbolAddress((void**)&vb,  g_v);
    cudaGetSymbolAddress((void**)&col, g_col);
    cudaGetSymbolAddress((void**)&gqv, g_gq);
    cudaGetSymbolAddress((void**)&gkv, g_gk);

    const int attn_smem = (2 * 64 * TSQ + 2 * 64 * TSK + 128 + 64) * (int)sizeof(float);
    cudaFuncSetAttribute(attn_kernel, cudaFuncAttributeMaxDynamicSharedMemorySize,
                         attn_smem);

    dim3 gemm_grid(DD / 128, MR / 128);   // (8, 32) = 256 CTAs

    ln_kernel<<<MR, 256>>>(x, lnw, lnb, xn);
    sgemm_kernel<<<gemm_grid, 256>>>(xn, Wq, nullptr, qb);
    sgemm_kernel<<<gemm_grid, 256>>>(xn, Wk, nullptr, kb);
    sgemm_kernel<<<gemm_grid, 256>>>(x,  Wv, nullptr, vb);
    qknorm_kernel<<<(MR * HH) / 8, 256>>>(qb, kb, gq, gk, gqv, gkv);
    attn_kernel<<<dim3(TT / 128, HH, BB), 256, attn_smem>>>(qb, kb, vb, gqv, gkv, col);
    sgemm_kernel<<<gemm_grid, 256>>>(col, Wo, bo, out);
}

// round 5
// speedup vs baseline: 1.2265x; 1.0276x over previous
#include <cuda_runtime.h>
#include <math.h>

#define DD 1024
#define HH 16
#define HDIM 64
#define TT 2048
#define BB 2
#define MR 4096            // B*T
#define THRESHF 0.29514f
#define SHARPF 15.0f

typedef unsigned long long u64t;

__device__ __forceinline__ u64t dup2(float x) {
    u64t r; asm("mov.b64 %0, {%1,%1};" : "=l"(r) : "f"(x)); return r;
}
__device__ __forceinline__ void fma2(u64t& d, u64t a, u64t b) {
    asm("fma.rn.f32x2 %0, %1, %2, %3;" : "=l"(d) : "l"(a), "l"(b), "l"(d));
}
__device__ __forceinline__ float2 unpk(u64t v) {
    float2 f; asm("mov.b64 {%0,%1}, %2;" : "=f"(f.x), "=f"(f.y) : "l"(v)); return f;
}

// -------------------- scratch (device globals; no allocation) --------------------
__device__ float g_xn[(size_t)MR * DD];
__device__ float g_q [(size_t)MR * DD];
__device__ float g_k [(size_t)MR * DD];
__device__ float g_v [(size_t)MR * DD];
__device__ float g_col[(size_t)MR * DD];
__device__ float g_gq[MR * HH];
__device__ float g_gk[MR * HH];

// -------------------- LayerNorm: one block per row --------------------
__global__ __launch_bounds__(256) void ln_kernel(const float* __restrict__ x,
                                                 const float* __restrict__ w,
                                                 const float* __restrict__ bia,
                                                 float* __restrict__ y) {
    int row = blockIdx.x;
    const float4* xr = (const float4*)(x + (size_t)row * DD);
    float4 v = xr[threadIdx.x];
    float sum = v.x + v.y + v.z + v.w;
    float sq  = v.x*v.x + v.y*v.y + v.z*v.z + v.w*v.w;
#pragma unroll
    for (int o = 16; o > 0; o >>= 1) {
        sum += __shfl_xor_sync(0xffffffffu, sum, o);
        sq  += __shfl_xor_sync(0xffffffffu, sq, o);
    }
    __shared__ float s1[8], s2[8];
    int wid = threadIdx.x >> 5;
    if ((threadIdx.x & 31) == 0) { s1[wid] = sum; s2[wid] = sq; }
    __syncthreads();
    sum = 0.f; sq = 0.f;
#pragma unroll
    for (int i = 0; i < 8; i++) { sum += s1[i]; sq += s2[i]; }
    float mean = sum * (1.0f / DD);
    float var  = sq * (1.0f / DD) - mean * mean;
    float inv  = rsqrtf(var + 1e-5f);
    float4 wv = ((const float4*)w)[threadIdx.x];
    float4 bv = ((const float4*)bia)[threadIdx.x];
    float4 o;
    o.x = (v.x - mean) * inv * wv.x + bv.x;
    o.y = (v.y - mean) * inv * wv.y + bv.y;
    o.z = (v.z - mean) * inv * wv.z + bv.z;
    o.w = (v.w - mean) * inv * wv.w + bv.w;
    ((float4*)(y + (size_t)row * DD))[threadIdx.x] = o;
}

// -------------------- SGEMM: C[M,N] = A[M,K] * W[K,N] (+bias) --------------------
// 128x128 block tile, BK=16, 256 threads, 8x8 microtile via fma.rn.f32x2.
__global__ __launch_bounds__(256, 2) void sgemm_kernel(const float* __restrict__ A,
                                                       const float* __restrict__ W,
                                                       const float* __restrict__ bias,
                                                       float* __restrict__ C) {
    __shared__ float As[16][128];   // [k][m] transposed
    __shared__ float Bs[16][128];   // [k][n]
    int tid = threadIdx.x;
    int tx = tid & 15, ty = tid >> 4;
    int m0 = blockIdx.y << 7, n0 = blockIdx.x << 7;

    int ar = tid >> 1;               // 0..127
    int ac = (tid & 1) << 3;         // 0 or 8
    int br = tid >> 4;               // 0..15
    int bc = (tid & 15) << 3;        // 0..120

    const float* Ap = A + (size_t)(m0 + ar) * DD + ac;
    const float* Wp = W + (size_t)br * DD + n0 + bc;

    u64t acc2[8][4] = {};   // rows i=0..7 (two m-quadrants), col-pairs j2 (two n-quadrants)

    float4 av0 = *(const float4*)(Ap);
    float4 av1 = *(const float4*)(Ap + 4);
    float4 bv0 = *(const float4*)(Wp);
    float4 bv1 = *(const float4*)(Wp + 4);

    for (int k0 = 0; k0 < DD; k0 += 16) {
        __syncthreads();
        As[ac + 0][ar] = av0.x;
        As[ac + 1][ar] = av0.y;
        As[ac + 2][ar] = av0.z;
        As[ac + 3][ar] = av0.w;
        As[ac + 4][ar] = av1.x;
        As[ac + 5][ar] = av1.y;
        As[ac + 6][ar] = av1.z;
        As[ac + 7][ar] = av1.w;
        *(float4*)&Bs[br][bc]     = bv0;
        *(float4*)&Bs[br][bc + 4] = bv1;
        __syncthreads();

        if (k0 + 16 < DD) {
            av0 = *(const float4*)(Ap + k0 + 16);
            av1 = *(const float4*)(Ap + k0 + 20);
            bv0 = *(const float4*)(Wp + (size_t)(k0 + 16) * DD);
            bv1 = *(const float4*)(Wp + (size_t)(k0 + 16) * DD + 4);
        }

#pragma unroll
        for (int kk = 0; kk < 16; kk++) {
            float a[8];
            *(float4*)&a[0] = *(const float4*)&As[kk][ty << 2];
            *(float4*)&a[4] = *(const float4*)&As[kk][64 + (ty << 2)];
            ulonglong2 b01 = *(const ulonglong2*)&Bs[kk][tx << 2];
            ulonglong2 b23 = *(const ulonglong2*)&Bs[kk][64 + (tx << 2)];
            u64t bp[4] = {b01.x, b01.y, b23.x, b23.y};
            u64t ad[8];
#pragma unroll
            for (int i = 0; i < 8; i++) ad[i] = dup2(a[i]);
#pragma unroll
            for (int i = 0; i < 8; i++)
#pragma unroll
                for (int j2 = 0; j2 < 4; j2++) fma2(acc2[i][j2], ad[i], bp[j2]);
        }
    }

    float4 bad0 = make_float4(0.f, 0.f, 0.f, 0.f);
    float4 bad1 = bad0;
    if (bias) {
        bad0 = *(const float4*)&bias[n0 + (tx << 2)];
        bad1 = *(const float4*)&bias[n0 + 64 + (tx << 2)];
    }
#pragma unroll
    for (int qi = 0; qi < 2; qi++) {
#pragma unroll
        for (int i = 0; i < 4; i++) {
            int row = m0 + qi * 64 + (ty << 2) + i;
            int ii = qi * 4 + i;
            float2 c0 = unpk(acc2[ii][0]);
            float2 c1 = unpk(acc2[ii][1]);
            float2 c2 = unpk(acc2[ii][2]);
            float2 c3 = unpk(acc2[ii][3]);
            float4 o0 = make_float4(c0.x + bad0.x, c0.y + bad0.y,
                                    c1.x + bad0.z, c1.y + bad0.w);
            float4 o1 = make_float4(c2.x + bad1.x, c2.y + bad1.y,
                                    c3.x + bad1.z, c3.y + bad1.w);
            *(float4*)&C[(size_t)row * DD + n0 + (tx << 2)]      = o0;
            *(float4*)&C[(size_t)row * DD + n0 + 64 + (tx << 2)] = o1;
        }
    }
}

// -------------------- L2 normalize q,k (64-elem heads) + gates; warp per (b,t,h) ----------
__global__ __launch_bounds__(256) void qknorm_kernel(float* __restrict__ q,
                                                     float* __restrict__ k,
                                                     const float* __restrict__ gqw,
                                                     const float* __restrict__ gkw,
                                                     float* __restrict__ gateq,
                                                     float* __restrict__ gatek) {
    int r = blockIdx.x * 8 + (threadIdx.x >> 5);   // flat (b*T+t)*H + h
    int lane = threadIdx.x & 31;
    size_t base = (size_t)r * HDIM + lane * 2;

    float2 g1 = *(const float2*)&gqw[lane * 2];
    float2 g2 = *(const float2*)&gkw[lane * 2];

    float2 qv = *(float2*)&q[base];
    float ss = qv.x * qv.x + qv.y * qv.y;
#pragma unroll
    for (int o = 16; o > 0; o >>= 1) ss += __shfl_xor_sync(0xffffffffu, ss, o);
    float inv = 1.0f / fmaxf(sqrtf(ss), 1e-12f);
    qv.x *= inv; qv.y *= inv;
    *(float2*)&q[base] = qv;
    float gd = qv.x * g1.x + qv.y * g1.y;
#pragma unroll
    for (int o = 16; o > 0; o >>= 1) gd += __shfl_xor_sync(0xffffffffu, gd, o);
    if (lane == 0) gateq[r] = gd;

    float2 kv = *(float2*)&k[base];
    ss = kv.x * kv.x + kv.y * kv.y;
#pragma unroll
    for (int o = 16; o > 0; o >>= 1) ss += __shfl_xor_sync(0xffffffffu, ss, o);
    inv = 1.0f / fmaxf(sqrtf(ss), 1e-12f);
    kv.x *= inv; kv.y *= inv;
    *(float2*)&k[base] = kv;
    gd = kv.x * g2.x + kv.y * g2.y;
#pragma unroll
    for (int o = 16; o > 0; o >>= 1) gd += __shfl_xor_sync(0xffffffffu, gd, o);
    if (lane == 0) gatek[r] = gd;
}

// -------------------- fused attention: 128(t) x 64(s) tiles, 8x4 microtile, f32x2 ----------
#define TSQ 132    // stride for 128-wide t-major rows (Qt, Ps)
#define TSK 68     // stride for 64-wide rows (Kt, Vs)
__global__ __launch_bounds__(256, 2) void attn_kernel(const float* __restrict__ q,
                                                      const float* __restrict__ k,
                                                      const float* __restrict__ v,
                                                      const float* __restrict__ gateq,
                                                      const float* __restrict__ gatek,
                                                      float* __restrict__ outc) {
    extern __shared__ float sm[];
    float* Qt  = sm;                        // [64 d][TSQ]  d-major (t cols)
    float* Ps  = Qt + 64 * TSQ;             // [64 s][TSQ]  t-major
    float* Kt  = Ps + 64 * TSQ;             // [64 d][TSK]  d-major (s cols)
    float* Vs  = Kt + 64 * TSK;             // [64 s][TSK]  row-major (d cols)
    float* gqs = Vs + 64 * TSK;             // [128]
    float* gks = gqs + 128;                 // [64]

    int tid = threadIdx.x;
    int tx = tid & 15, ty = tid >> 4;       // tx: s/d cols (4), ty: t rows (4+4)
    int t0 = blockIdx.x << 7;
    int h = blockIdx.y, b = blockIdx.z;
    size_t headoff = (size_t)b * TT * DD + (size_t)h * HDIM;

    // load Q tile transposed (d-major): 128 rows x 64 d
    for (int u = tid; u < 128 * 16; u += 256) {
        int r = u >> 4, c = (u & 15) << 2;
        float4 qv = *(const float4*)&q[headoff + (size_t)(t0 + r) * DD + c];
        Qt[(c + 0) * TSQ + r] = qv.x;
        Qt[(c + 1) * TSQ + r] = qv.y;
        Qt[(c + 2) * TSQ + r] = qv.z;
        Qt[(c + 3) * TSQ + r] = qv.w;
    }
    if (tid < 128) gqs[tid] = gateq[(size_t)(b * TT + t0 + tid) * HH + h];

    u64t acc0p[2][4] = {};   // t-row pairs (ty*4 + 2*i2, +1), d cols tx*4+c
    u64t acc1p[2][4] = {};   // t-row pairs at +64

    for (int s0 = 0; s0 < TT; s0 += 64) {
        __syncthreads();   // prev PV done reading Vs/Ps
        for (int u = tid; u < 64 * 16; u += 256) {
            int r = u >> 4, c = (u & 15) << 2;
            size_t ga = headoff + (size_t)(s0 + r) * DD + c;
            float4 kv = *(const float4*)&k[ga];
            Kt[(c + 0) * TSK + r] = kv.x;
            Kt[(c + 1) * TSK + r] = kv.y;
            Kt[(c + 2) * TSK + r] = kv.z;
            Kt[(c + 3) * TSK + r] = kv.w;
            float4 vv = *(const float4*)&v[ga];
            *(float4*)&Vs[r * TSK + c] = vv;
        }
        if (tid < 64) gks[tid] = gatek[(size_t)(b * TT + s0 + tid) * HH + h];
        __syncthreads();

        // S = Q K^T : t-row pairs packed, s cols tx*4+j scalar
        u64t s0p[2][4] = {}, s1p[2][4] = {};
#pragma unroll 8
        for (int d = 0; d < 64; d++) {
            ulonglong2 a0 = *(const ulonglong2*)&Qt[d * TSQ + (ty << 2)];
            ulonglong2 a1 = *(const ulonglong2*)&Qt[d * TSQ + 64 + (ty << 2)];
            float bb[4];
            *(float4*)&bb[0] = *(const float4*)&Kt[d * TSK + (tx << 2)];
            u64t bd[4];
#pragma unroll
            for (int j = 0; j < 4; j++) bd[j] = dup2(bb[j]);
            u64t a0p[2] = {a0.x, a0.y};
            u64t a1p[2] = {a1.x, a1.y};
#pragma unroll
            for (int i2 = 0; i2 < 2; i2++)
#pragma unroll
                for (int j = 0; j < 4; j++) {
                    fma2(s0p[i2][j], a0p[i2], bd[j]);
                    fma2(s1p[i2][j], a1p[i2], bd[j]);
                }
        }

        // modulation -> Ps (t-major rows per s)
        float gq0[4], gq1[4], gk4[4];
        *(float4*)&gq0[0] = *(const float4*)&gqs[ty << 2];
        *(float4*)&gq1[0] = *(const float4*)&gqs[64 + (ty << 2)];
        *(float4*)&gk4[0] = *(const float4*)&gks[tx << 2];
#pragma unroll
        for (int j = 0; j < 4; j++) {
            float2 sa = unpk(s0p[0][j]);
            float2 sb = unpk(s0p[1][j]);
            float2 sc = unpk(s1p[0][j]);
            float2 sd = unpk(s1p[1][j]);
            float sv0[4] = {sa.x, sa.y, sb.x, sb.y};
            float sv1[4] = {sc.x, sc.y, sd.x, sd.y};
            float p0[4], p1[4];
#pragma unroll
            for (int i = 0; i < 4; i++) {
                float z0 = (sv0[i] - THRESHF) * SHARPF;
                float sg0 = __fdividef(1.0f, 1.0f + __expf(-z0));
                p0[i] = sg0 * gq0[i] * gk4[j];
                float z1 = (sv1[i] - THRESHF) * SHARPF;
                float sg1 = __fdividef(1.0f, 1.0f + __expf(-z1));
                p1[i] = sg1 * gq1[i] * gk4[j];
            }
            *(float4*)&Ps[((tx << 2) + j) * TSQ + (ty << 2)] =
                make_float4(p0[0], p0[1], p0[2], p0[3]);
            *(float4*)&Ps[((tx << 2) + j) * TSQ + 64 + (ty << 2)] =
                make_float4(p1[0], p1[1], p1[2], p1[3]);
        }
        __syncthreads();

        // acc += P @ V : t-row pairs packed, d cols dup'd
#pragma unroll 8
        for (int s = 0; s < 64; s++) {
            ulonglong2 p0 = *(const ulonglong2*)&Ps[s * TSQ + (ty << 2)];
            ulonglong2 p1 = *(const ulonglong2*)&Ps[s * TSQ + 64 + (ty << 2)];
            float vv[4];
            *(float4*)&vv[0] = *(const float4*)&Vs[s * TSK + (tx << 2)];
            u64t vd[4];
#pragma unroll
            for (int c = 0; c < 4; c++) vd[c] = dup2(vv[c]);
            u64t p0p[2] = {p0.x, p0.y};
            u64t p1p[2] = {p1.x, p1.y};
#pragma unroll
            for (int i2 = 0; i2 < 2; i2++)
#pragma unroll
                for (int c = 0; c < 4; c++) {
                    fma2(acc0p[i2][c], p0p[i2], vd[c]);
                    fma2(acc1p[i2][c], p1p[i2], vd[c]);
                }
        }
    }

#pragma unroll
    for (int i = 0; i < 4; i++) {
        float2 u0 = unpk(acc0p[i >> 1][0]);
        float2 u1 = unpk(acc0p[i >> 1][1]);
        float2 u2 = unpk(acc0p[i >> 1][2]);
        float2 u3 = unpk(acc0p[i >> 1][3]);
        float4 o0 = (i & 1) ? make_float4(u0.y, u1.y, u2.y, u3.y)
                            : make_float4(u0.x, u1.x, u2.x, u3.x);
        // NOTE: acc layout is [pair over rows][col]; row i uses half (i&1) of pair i>>1
        *(float4*)&outc[headoff + (size_t)(t0 + (ty << 2) + i) * DD + (tx << 2)] = o0;
        float2 w0 = unpk(acc1p[i >> 1][0]);
        float2 w1 = unpk(acc1p[i >> 1][1]);
        float2 w2 = unpk(acc1p[i >> 1][2]);
        float2 w3 = unpk(acc1p[i >> 1][3]);
        float4 o1 = (i & 1) ? make_float4(w0.y, w1.y, w2.y, w3.y)
                            : make_float4(w0.x, w1.x, w2.x, w3.x);
        *(float4*)&outc[headoff + (size_t)(t0 + 64 + (ty << 2) + i) * DD + (tx << 2)] = o1;
    }
}

// -------------------- launch --------------------
extern "C" void kernel_launch(void* const* d_in, const int* in_sizes, int n_in,
                              void* d_out, int out_size) {
    (void)in_sizes; (void)n_in; (void)out_size;
    const float* x   = (const float*)d_in[0];
    const float* Wq  = (const float*)d_in[1];
    const float* Wk  = (const float*)d_in[2];
    const float* Wv  = (const float*)d_in[3];
    const float* gq  = (const float*)d_in[4];
    const float* gk  = (const float*)d_in[5];
    const float* Wo  = (const float*)d_in[6];
    const float* bo  = (const float*)d_in[7];
    const float* lnw = (const float*)d_in[8];
    const float* lnb = (const float*)d_in[9];
    float* out = (float*)d_out;

    float *xn, *qb, *kb, *vb, *col, *gqv, *gkv;
    cudaGetSymbolAddress((void**)&xn,  g_xn);
    cudaGetSymbolAddress((void**)&qb,  g_q);
    cudaGetSymbolAddress((void**)&kb,  g_k);
    cudaGetSymbolAddress((void**)&vb,  g_v);
    cudaGetSymbolAddress((void**)&col, g_col);
    cudaGetSymbolAddress((void**)&gqv, g_gq);
    cudaGetSymbolAddress((void**)&gkv, g_gk);

    const int attn_smem = (2 * 64 * TSQ + 2 * 64 * TSK + 128 + 64) * (int)sizeof(float);
    cudaFuncSetAttribute(attn_kernel, cudaFuncAttributeMaxDynamicSharedMemorySize,
                         attn_smem);

    dim3 gemm_grid(DD / 128, MR / 128);   // (8, 32) = 256 CTAs

    ln_kernel<<<MR, 256>>>(x, lnw, lnb, xn);
    sgemm_kernel<<<gemm_grid, 256>>>(xn, Wq, nullptr, qb);
    sgemm_kernel<<<gemm_grid, 256>>>(xn, Wk, nullptr, kb);
    sgemm_kernel<<<gemm_grid, 256>>>(x,  Wv, nullptr, vb);
    qknorm_kernel<<<(MR * HH) / 8, 256>>>(qb, kb, gq, gk, gqv, gkv);
    attn_kernel<<<dim3(TT / 128, HH, BB), 256, attn_smem>>>(qb, kb, vb, gqv, gkv, col);
    sgemm_kernel<<<gemm_grid, 256>>>(col, Wo, bo, out);
}

// round 7
// speedup vs baseline: 1.4804x; 1.2070x over previous
#include <cuda_runtime.h>
#include <cuda_bf16.h>
#include <math.h>
#include <stdint.h>

#define DD 1024
#define HH 16
#define HDIM 64
#define TT 2048
#define BB 2
#define MR 4096            // B*T
#define THRESHF 0.29514f
#define SHARPF 15.0f

typedef unsigned long long u64t;

__device__ __forceinline__ u64t dup2(float x) {
    u64t r; asm("mov.b64 %0, {%1,%1};" : "=l"(r) : "f"(x)); return r;
}
__device__ __forceinline__ void fma2(u64t& d, u64t a, u64t b) {
    asm("fma.rn.f32x2 %0, %1, %2, %3;" : "=l"(d) : "l"(a), "l"(b), "l"(d));
}
__device__ __forceinline__ float2 unpk(u64t v) {
    float2 f; asm("mov.b64 {%0,%1}, %2;" : "=f"(f.x), "=f"(f.y) : "l"(v)); return f;
}

// ---------------- mma.sync helpers (target-portable; no sm_103a-only features) -----------
__device__ __forceinline__ uint32_t s2u(const void* p) {
    uint32_t a;
    asm("{ .reg .u64 t; cvta.to.shared.u64 t, %1; cvt.u32.u64 %0, t; }" : "=r"(a) : "l"(p));
    return a;
}
#define SWZ(o) ((o) ^ (((o) >> 3) & 0x70))

__device__ __forceinline__ void ldsm4(uint32_t* r, uint32_t addr) {
    asm volatile("ldmatrix.sync.aligned.m8n8.x4.shared.b16 {%0,%1,%2,%3}, [%4];"
                 : "=r"(r[0]), "=r"(r[1]), "=r"(r[2]), "=r"(r[3]) : "r"(addr));
}
__device__ __forceinline__ void mma16816(float* d, const uint32_t* a, const uint32_t* b) {
    asm volatile("mma.sync.aligned.m16n8k16.row.col.f32.bf16.bf16.f32 "
                 "{%0,%1,%2,%3}, {%4,%5,%6,%7}, {%8,%9}, {%0,%1,%2,%3};"
                 : "+f"(d[0]), "+f"(d[1]), "+f"(d[2]), "+f"(d[3])
                 : "r"(a[0]), "r"(a[1]), "r"(a[2]), "r"(a[3]), "r"(b[0]), "r"(b[1]));
}

__device__ __forceinline__ void split1(float v, __nv_bfloat16& h, __nv_bfloat16& l) {
    h = __float2bfloat16(v);
    l = __float2bfloat16(v - __bfloat162float(h));
}

// -------------------- scratch (device globals; no allocation) --------------------
__device__ float g_q [(size_t)MR * DD];
__device__ float g_k [(size_t)MR * DD];
__device__ float g_v [(size_t)MR * DD];
__device__ float g_gq[MR * HH];
__device__ float g_gk[MR * HH];
__device__ __nv_bfloat16 g_xnhi[(size_t)MR * DD];
__device__ __nv_bfloat16 g_xnlo[(size_t)MR * DD];
__device__ __nv_bfloat16 g_xhi [(size_t)MR * DD];
__device__ __nv_bfloat16 g_xlo [(size_t)MR * DD];
__device__ __nv_bfloat16 g_chi [(size_t)MR * DD];
__device__ __nv_bfloat16 g_clo [(size_t)MR * DD];
__device__ __nv_bfloat16 g_wthi[(size_t)4 * DD * DD];   // [w][n][k]
__device__ __nv_bfloat16 g_wtlo[(size_t)4 * DD * DD];

// -------------------- LayerNorm: one block per row; emits bf16 hi/lo splits ----------
__global__ __launch_bounds__(256) void ln_kernel(const float* __restrict__ x,
                                                 const float* __restrict__ w,
                                                 const float* __restrict__ bia,
                                                 __nv_bfloat16* __restrict__ yhi,
                                                 __nv_bfloat16* __restrict__ ylo) {
    int row = blockIdx.x;
    const float4* xr = (const float4*)(x + (size_t)row * DD);
    float4 v = xr[threadIdx.x];
    float sum = v.x + v.y + v.z + v.w;
    float sq  = v.x*v.x + v.y*v.y + v.z*v.z + v.w*v.w;
#pragma unroll
    for (int o = 16; o > 0; o >>= 1) {
        sum += __shfl_xor_sync(0xffffffffu, sum, o);
        sq  += __shfl_xor_sync(0xffffffffu, sq, o);
    }
    __shared__ float s1[8], s2[8];
    int wid = threadIdx.x >> 5;
    if ((threadIdx.x & 31) == 0) { s1[wid] = sum; s2[wid] = sq; }
    __syncthreads();
    sum = 0.f; sq = 0.f;
#pragma unroll
    for (int i = 0; i < 8; i++) { sum += s1[i]; sq += s2[i]; }
    float mean = sum * (1.0f / DD);
    float var  = sq * (1.0f / DD) - mean * mean;
    float inv  = rsqrtf(var + 1e-5f);
    float4 wv = ((const float4*)w)[threadIdx.x];
    float4 bv = ((const float4*)bia)[threadIdx.x];
    float o[4];
    o[0] = (v.x - mean) * inv * wv.x + bv.x;
    o[1] = (v.y - mean) * inv * wv.y + bv.y;
    o[2] = (v.z - mean) * inv * wv.z + bv.z;
    o[3] = (v.w - mean) * inv * wv.w + bv.w;
    size_t idx = (size_t)row * DD + threadIdx.x * 4;
    __nv_bfloat16 h[4], l[4];
#pragma unroll
    for (int i = 0; i < 4; i++) split1(o[i], h[i], l[i]);
    *(__nv_bfloat162*)&yhi[idx]     = __nv_bfloat162(h[0], h[1]);
    *(__nv_bfloat162*)&yhi[idx + 2] = __nv_bfloat162(h[2], h[3]);
    *(__nv_bfloat162*)&ylo[idx]     = __nv_bfloat162(l[0], l[1]);
    *(__nv_bfloat162*)&ylo[idx + 2] = __nv_bfloat162(l[2], l[3]);
}

// -------------------- elementwise split: fp32 -> hi/lo bf16 --------------------
__global__ __launch_bounds__(256) void split_kernel(const float* __restrict__ in,
                                                    __nv_bfloat16* __restrict__ hi,
                                                    __nv_bfloat16* __restrict__ lo) {
    int i = blockIdx.x * 256 + threadIdx.x;
    float4 v = ((const float4*)in)[i];
    float o[4] = {v.x, v.y, v.z, v.w};
    __nv_bfloat16 h[4], l[4];
#pragma unroll
    for (int j = 0; j < 4; j++) split1(o[j], h[j], l[j]);
    size_t idx = (size_t)i * 4;
    *(__nv_bfloat162*)&hi[idx]     = __nv_bfloat162(h[0], h[1]);
    *(__nv_bfloat162*)&hi[idx + 2] = __nv_bfloat162(h[2], h[3]);
    *(__nv_bfloat162*)&lo[idx]     = __nv_bfloat162(l[0], l[1]);
    *(__nv_bfloat162*)&lo[idx + 2] = __nv_bfloat162(l[2], l[3]);
}

// -------------------- weight transpose + split: W[k][n] -> Wt_hi/lo[n][k] ------------
__global__ void wtsplit_kernel(const float* __restrict__ W,
                               __nv_bfloat16* __restrict__ Whi,
                               __nv_bfloat16* __restrict__ Wlo) {
    __shared__ float t[32][33];
    int n0 = blockIdx.x * 32, k0 = blockIdx.y * 32;
    int tx = threadIdx.x, ty = threadIdx.y;   // (32, 8)
#pragma unroll
    for (int j = 0; j < 32; j += 8)
        t[ty + j][tx] = W[(size_t)(k0 + ty + j) * DD + n0 + tx];
    __syncthreads();
#pragma unroll
    for (int j = 0; j < 32; j += 8) {
        float v = t[tx][ty + j];
        __nv_bfloat16 h, l;
        split1(v, h, l);
        size_t o = (size_t)(n0 + ty + j) * DD + k0 + tx;
        Whi[o] = h; Wlo[o] = l;
    }
}

// -------------------- mma.sync GEMM: C[M,N] = A[M,K] * Wt[N,K]^T  (split-bf16 x3) ------
// 128x128 tile, BK=64, 8 warps, warp tile 64x32 (4 m-tiles x 4 n-tiles of m16n8k16).
#define TGA  0
#define TGAL 16384
#define TGB  32768
#define TGBL 49152
#define TG_SMEM 65536
__global__ __launch_bounds__(256) void tgemm_kernel(
    const __nv_bfloat16* __restrict__ Ahi, const __nv_bfloat16* __restrict__ Alo,
    const __nv_bfloat16* __restrict__ Bhi, const __nv_bfloat16* __restrict__ Blo,
    const float* __restrict__ bias, float* __restrict__ C) {
    extern __shared__ char smem[];
    uint32_t sb = s2u(smem);
    int tid = threadIdx.x, wid = tid >> 5, lane = tid & 31;
    int m0 = blockIdx.y << 7, n0 = blockIdx.x << 7;
    int wm = (wid & 1) << 6;      // 0 or 64
    int wn = (wid >> 1) << 5;     // 0,32,64,96

    float acc[4][4][4] = {};      // [mt][nt][c0,c1,c2,c3]

    // precomputed ldmatrix lane addressing
    int a_row = (lane & 15);
    int a_koff = (lane >> 4) << 4;               // 0 or 16 bytes
    int b_row = ((lane >> 4) << 3) + (lane & 7); // 0..15 within 16-n group
    int b_koff = ((lane >> 3) & 1) << 4;         // 0 or 16 bytes

    for (int kc = 0; kc < 16; kc++) {
        int k0 = kc << 6;
        __syncthreads();
        for (int u = tid; u < 1024; u += 256) {
            int r = u >> 3, s = u & 7;
            uint32_t doff = SWZ((r << 7) + (s << 4));
            size_t ga = ((size_t)(m0 + r) << 10) + k0 + (s << 3);
            size_t gb = ((size_t)(n0 + r) << 10) + k0 + (s << 3);
            *(uint4*)(smem + TGA  + doff) = *(const uint4*)(Ahi + ga);
            *(uint4*)(smem + TGAL + doff) = *(const uint4*)(Alo + ga);
            *(uint4*)(smem + TGB  + doff) = *(const uint4*)(Bhi + gb);
            *(uint4*)(smem + TGBL + doff) = *(const uint4*)(Blo + gb);
        }
        __syncthreads();

#pragma unroll
        for (int ks = 0; ks < 4; ks++) {
            int kb = ks << 5;   // byte offset of this k-step within 128B row
            uint32_t af[4][4];
            uint32_t bh[4][2], bl[4][2];
            // B frags: 2x ldmatrix.x4, each covers two n-tiles (hi and lo)
#pragma unroll
            for (int nt2 = 0; nt2 < 2; nt2++) {
                int nrow = wn + (nt2 << 4) + b_row;
                uint32_t off = SWZ((nrow << 7) + kb + b_koff);
                uint32_t r4[4];
                ldsm4(r4, sb + TGB + off);
                bh[nt2 * 2][0] = r4[0]; bh[nt2 * 2][1] = r4[1];
                bh[nt2 * 2 + 1][0] = r4[2]; bh[nt2 * 2 + 1][1] = r4[3];
                ldsm4(r4, sb + TGBL + off);
                bl[nt2 * 2][0] = r4[0]; bl[nt2 * 2][1] = r4[1];
                bl[nt2 * 2 + 1][0] = r4[2]; bl[nt2 * 2 + 1][1] = r4[3];
            }
            // A-hi frags, then hi*hi and hi*lo terms
#pragma unroll
            for (int mt = 0; mt < 4; mt++) {
                int row = wm + (mt << 4) + a_row;
                ldsm4(af[mt], sb + TGA + SWZ((row << 7) + kb + a_koff));
            }
#pragma unroll
            for (int mt = 0; mt < 4; mt++)
#pragma unroll
                for (int nt = 0; nt < 4; nt++) {
                    mma16816(acc[mt][nt], af[mt], bh[nt]);
                    mma16816(acc[mt][nt], af[mt], bl[nt]);
                }
            // A-lo frags (reuse af regs), lo*hi term
#pragma unroll
            for (int mt = 0; mt < 4; mt++) {
                int row = wm + (mt << 4) + a_row;
                ldsm4(af[mt], sb + TGAL + SWZ((row << 7) + kb + a_koff));
            }
#pragma unroll
            for (int mt = 0; mt < 4; mt++)
#pragma unroll
                for (int nt = 0; nt < 4; nt++)
                    mma16816(acc[mt][nt], af[mt], bh[nt]);
        }
    }

    // epilogue: direct register -> gmem (C fragment layout), optional bias
    int g = lane >> 2, t4 = lane & 3;
#pragma unroll
    for (int mt = 0; mt < 4; mt++) {
#pragma unroll
        for (int nt = 0; nt < 4; nt++) {
            int col = n0 + wn + (nt << 3) + (t4 << 1);
            float bx = 0.f, by = 0.f;
            if (bias) { float2 bv = *(const float2*)&bias[col]; bx = bv.x; by = bv.y; }
            int r0 = m0 + wm + (mt << 4) + g;
            *(float2*)&C[((size_t)r0 << 10) + col] =
                make_float2(acc[mt][nt][0] + bx, acc[mt][nt][1] + by);
            *(float2*)&C[((size_t)(r0 + 8) << 10) + col] =
                make_float2(acc[mt][nt][2] + bx, acc[mt][nt][3] + by);
        }
    }
}

// -------------------- L2 normalize q,k (64-elem heads) + gates; warp per (b,t,h) ----------
__global__ __launch_bounds__(256) void qknorm_kernel(float* __restrict__ q,
                                                     float* __restrict__ k,
                                                     const float* __restrict__ gqw,
                                                     const float* __restrict__ gkw,
                                                     float* __restrict__ gateq,
                                                     float* __restrict__ gatek) {
    int r = blockIdx.x * 8 + (threadIdx.x >> 5);
    int lane = threadIdx.x & 31;
    size_t base = (size_t)r * HDIM + lane * 2;

    float2 g1 = *(const float2*)&gqw[lane * 2];
    float2 g2 = *(const float2*)&gkw[lane * 2];

    float2 qv = *(float2*)&q[base];
    float ss = qv.x * qv.x + qv.y * qv.y;
#pragma unroll
    for (int o = 16; o > 0; o >>= 1) ss += __shfl_xor_sync(0xffffffffu, ss, o);
    float inv = 1.0f / fmaxf(sqrtf(ss), 1e-12f);
    qv.x *= inv; qv.y *= inv;
    *(float2*)&q[base] = qv;
    float gd = qv.x * g1.x + qv.y * g1.y;
#pragma unroll
    for (int o = 16; o > 0; o >>= 1) gd += __shfl_xor_sync(0xffffffffu, gd, o);
    if (lane == 0) gateq[r] = gd;

    float2 kv = *(float2*)&k[base];
    ss = kv.x * kv.x + kv.y * kv.y;
#pragma unroll
    for (int o = 16; o > 0; o >>= 1) ss += __shfl_xor_sync(0xffffffffu, ss, o);
    inv = 1.0f / fmaxf(sqrtf(ss), 1e-12f);
    kv.x *= inv; kv.y *= inv;
    *(float2*)&k[base] = kv;
    gd = kv.x * g2.x + kv.y * g2.y;
#pragma unroll
    for (int o = 16; o > 0; o >>= 1) gd += __shfl_xor_sync(0xffffffffu, gd, o);
    if (lane == 0) gatek[r] = gd;
}

// -------------------- fused attention: 128(t) x 64(s) tiles, f32x2; emits bf16 splits ----
#define TSQ 132
#define TSK 68
__global__ __launch_bounds__(256, 2) void attn_kernel(const float* __restrict__ q,
                                                      const float* __restrict__ k,
                                                      const float* __restrict__ v,
                                                      const float* __restrict__ gateq,
                                                      const float* __restrict__ gatek,
                                                      __nv_bfloat16* __restrict__ ohi,
                                                      __nv_bfloat16* __restrict__ olo) {
    extern __shared__ float sm[];
    float* Qt  = sm;
    float* Ps  = Qt + 64 * TSQ;
    float* Kt  = Ps + 64 * TSQ;
    float* Vs  = Kt + 64 * TSK;
    float* gqs = Vs + 64 * TSK;
    float* gks = gqs + 128;

    int tid = threadIdx.x;
    int tx = tid & 15, ty = tid >> 4;
    int t0 = blockIdx.x << 7;
    int h = blockIdx.y, b = blockIdx.z;
    size_t headoff = (size_t)b * TT * DD + (size_t)h * HDIM;

    for (int u = tid; u < 128 * 16; u += 256) {
        int r = u >> 4, c = (u & 15) << 2;
        float4 qv = *(const float4*)&q[headoff + (size_t)(t0 + r) * DD + c];
        Qt[(c + 0) * TSQ + r] = qv.x;
        Qt[(c + 1) * TSQ + r] = qv.y;
        Qt[(c + 2) * TSQ + r] = qv.z;
        Qt[(c + 3) * TSQ + r] = qv.w;
    }
    if (tid < 128) gqs[tid] = gateq[(size_t)(b * TT + t0 + tid) * HH + h];

    u64t acc0p[2][4] = {};
    u64t acc1p[2][4] = {};

    for (int s0 = 0; s0 < TT; s0 += 64) {
        __syncthreads();
        for (int u = tid; u < 64 * 16; u += 256) {
            int r = u >> 4, c = (u & 15) << 2;
            size_t ga = headoff + (size_t)(s0 + r) * DD + c;
            float4 kv = *(const float4*)&k[ga];
            Kt[(c + 0) * TSK + r] = kv.x;
            Kt[(c + 1) * TSK + r] = kv.y;
            Kt[(c + 2) * TSK + r] = kv.z;
            Kt[(c + 3) * TSK + r] = kv.w;
            float4 vv = *(const float4*)&v[ga];
            *(float4*)&Vs[r * TSK + c] = vv;
        }
        if (tid < 64) gks[tid] = gatek[(size_t)(b * TT + s0 + tid) * HH + h];
        __syncthreads();

        u64t s0p[2][4] = {}, s1p[2][4] = {};
#pragma unroll 8
        for (int d = 0; d < 64; d++) {
            ulonglong2 a0 = *(const ulonglong2*)&Qt[d * TSQ + (ty << 2)];
            ulonglong2 a1 = *(const ulonglong2*)&Qt[d * TSQ + 64 + (ty << 2)];
            float bb[4];
            *(float4*)&bb[0] = *(const float4*)&Kt[d * TSK + (tx << 2)];
            u64t bd[4];
#pragma unroll
            for (int j = 0; j < 4; j++) bd[j] = dup2(bb[j]);
            u64t a0p[2] = {a0.x, a0.y};
            u64t a1p[2] = {a1.x, a1.y};
#pragma unroll
            for (int i2 = 0; i2 < 2; i2++)
#pragma unroll
                for (int j = 0; j < 4; j++) {
                    fma2(s0p[i2][j], a0p[i2], bd[j]);
                    fma2(s1p[i2][j], a1p[i2], bd[j]);
                }
        }

        float gq0[4], gq1[4], gk4[4];
        *(float4*)&gq0[0] = *(const float4*)&gqs[ty << 2];
        *(float4*)&gq1[0] = *(const float4*)&gqs[64 + (ty << 2)];
        *(float4*)&gk4[0] = *(const float4*)&gks[tx << 2];
#pragma unroll
        for (int j = 0; j < 4; j++) {
            float2 sa = unpk(s0p[0][j]);
            float2 sb = unpk(s0p[1][j]);
            float2 sc = unpk(s1p[0][j]);
            float2 sd = unpk(s1p[1][j]);
            float sv0[4] = {sa.x, sa.y, sb.x, sb.y};
            float sv1[4] = {sc.x, sc.y, sd.x, sd.y};
            float p0[4], p1[4];
#pragma unroll
            for (int i = 0; i < 4; i++) {
                float z0 = (sv0[i] - THRESHF) * SHARPF;
                float sg0 = __fdividef(1.0f, 1.0f + __expf(-z0));
                p0[i] = sg0 * gq0[i] * gk4[j];
                float z1 = (sv1[i] - THRESHF) * SHARPF;
                float sg1 = __fdividef(1.0f, 1.0f + __expf(-z1));
                p1[i] = sg1 * gq1[i] * gk4[j];
            }
            *(float4*)&Ps[((tx << 2) + j) * TSQ + (ty << 2)] =
                make_float4(p0[0], p0[1], p0[2], p0[3]);
            *(float4*)&Ps[((tx << 2) + j) * TSQ + 64 + (ty << 2)] =
                make_float4(p1[0], p1[1], p1[2], p1[3]);
        }
        __syncthreads();

#pragma unroll 8
        for (int s = 0; s < 64; s++) {
            ulonglong2 p0 = *(const ulonglong2*)&Ps[s * TSQ + (ty << 2)];
            ulonglong2 p1 = *(const ulonglong2*)&Ps[s * TSQ + 64 + (ty << 2)];
            float vv[4];
            *(float4*)&vv[0] = *(const float4*)&Vs[s * TSK + (tx << 2)];
            u64t vd[4];
#pragma unroll
            for (int c = 0; c < 4; c++) vd[c] = dup2(vv[c]);
            u64t p0p[2] = {p0.x, p0.y};
            u64t p1p[2] = {p1.x, p1.y};
#pragma unroll
            for (int i2 = 0; i2 < 2; i2++)
#pragma unroll
                for (int c = 0; c < 4; c++) {
                    fma2(acc0p[i2][c], p0p[i2], vd[c]);
                    fma2(acc1p[i2][c], p1p[i2], vd[c]);
                }
        }
    }

#pragma unroll
    for (int i = 0; i < 4; i++) {
        float2 u0 = unpk(acc0p[i >> 1][0]);
        float2 u1 = unpk(acc0p[i >> 1][1]);
        float2 u2 = unpk(acc0p[i >> 1][2]);
        float2 u3 = unpk(acc0p[i >> 1][3]);
        float o0[4];
        if (i & 1) { o0[0] = u0.y; o0[1] = u1.y; o0[2] = u2.y; o0[3] = u3.y; }
        else       { o0[0] = u0.x; o0[1] = u1.x; o0[2] = u2.x; o0[3] = u3.x; }
        size_t idx0 = headoff + (size_t)(t0 + (ty << 2) + i) * DD + (tx << 2);
        __nv_bfloat16 hh[4], ll[4];
#pragma unroll
        for (int c = 0; c < 4; c++) split1(o0[c], hh[c], ll[c]);
        *(__nv_bfloat162*)&ohi[idx0]     = __nv_bfloat162(hh[0], hh[1]);
        *(__nv_bfloat162*)&ohi[idx0 + 2] = __nv_bfloat162(hh[2], hh[3]);
        *(__nv_bfloat162*)&olo[idx0]     = __nv_bfloat162(ll[0], ll[1]);
        *(__nv_bfloat162*)&olo[idx0 + 2] = __nv_bfloat162(ll[2], ll[3]);

        float2 w0 = unpk(acc1p[i >> 1][0]);
        float2 w1 = unpk(acc1p[i >> 1][1]);
        float2 w2 = unpk(acc1p[i >> 1][2]);
        float2 w3 = unpk(acc1p[i >> 1][3]);
        float o1[4];
        if (i & 1) { o1[0] = w0.y; o1[1] = w1.y; o1[2] = w2.y; o1[3] = w3.y; }
        else       { o1[0] = w0.x; o1[1] = w1.x; o1[2] = w2.x; o1[3] = w3.x; }
        size_t idx1 = headoff + (size_t)(t0 + 64 + (ty << 2) + i) * DD + (tx << 2);
#pragma unroll
        for (int c = 0; c < 4; c++) split1(o1[c], hh[c], ll[c]);
        *(__nv_bfloat162*)&ohi[idx1]     = __nv_bfloat162(hh[0], hh[1]);
        *(__nv_bfloat162*)&ohi[idx1 + 2] = __nv_bfloat162(hh[2], hh[3]);
        *(__nv_bfloat162*)&olo[idx1]     = __nv_bfloat162(ll[0], ll[1]);
        *(__nv_bfloat162*)&olo[idx1 + 2] = __nv_bfloat162(ll[2], ll[3]);
    }
}

// -------------------- launch --------------------
extern "C" void kernel_launch(void* const* d_in, const int* in_sizes, int n_in,
                              void* d_out, int out_size) {
    (void)in_sizes; (void)n_in; (void)out_size;
    const float* x   = (const float*)d_in[0];
    const float* Wq  = (const float*)d_in[1];
    const float* Wk  = (const float*)d_in[2];
    const float* Wv  = (const float*)d_in[3];
    const float* gq  = (const float*)d_in[4];
    const float* gk  = (const float*)d_in[5];
    const float* Wo  = (const float*)d_in[6];
    const float* bo  = (const float*)d_in[7];
    const float* lnw = (const float*)d_in[8];
    const float* lnb = (const float*)d_in[9];
    float* out = (float*)d_out;

    float *qb, *kb, *vb, *gqv, *gkv;
    __nv_bfloat16 *xnhi, *xnlo, *xhi, *xlo, *chi, *clo, *wthi, *wtlo;
    cudaGetSymbolAddress((void**)&qb,   g_q);
    cudaGetSymbolAddress((void**)&kb,   g_k);
    cudaGetSymbolAddress((void**)&vb,   g_v);
    cudaGetSymbolAddress((void**)&gqv,  g_gq);
    cudaGetSymbolAddress((void**)&gkv,  g_gk);
    cudaGetSymbolAddress((void**)&xnhi, g_xnhi);
    cudaGetSymbolAddress((void**)&xnlo, g_xnlo);
    cudaGetSymbolAddress((void**)&xhi,  g_xhi);
    cudaGetSymbolAddress((void**)&xlo,  g_xlo);
    cudaGetSymbolAddress((void**)&chi,  g_chi);
    cudaGetSymbolAddress((void**)&clo,  g_clo);
    cudaGetSymbolAddress((void**)&wthi, g_wthi);
    cudaGetSymbolAddress((void**)&wtlo, g_wtlo);

    const size_t WSZ = (size_t)DD * DD;

    const int attn_smem = (2 * 64 * TSQ + 2 * 64 * TSK + 128 + 64) * (int)sizeof(float);
    cudaFuncSetAttribute(attn_kernel, cudaFuncAttributeMaxDynamicSharedMemorySize,
                         attn_smem);
    cudaFuncSetAttribute(tgemm_kernel, cudaFuncAttributeMaxDynamicSharedMemorySize,
                         TG_SMEM);

    dim3 tgrid(DD / 128, MR / 128);       // (8, 32)
    dim3 wtgrid(DD / 32, DD / 32);        // (32, 32)
    dim3 wtblk(32, 8);

    // prep
    ln_kernel<<<MR, 256>>>(x, lnw, lnb, xnhi, xnlo);
    split_kernel<<<(MR * DD) / (256 * 4), 256>>>(x, xhi, xlo);
    wtsplit_kernel<<<wtgrid, wtblk>>>(Wq, wthi + 0 * WSZ, wtlo + 0 * WSZ);
    wtsplit_kernel<<<wtgrid, wtblk>>>(Wk, wthi + 1 * WSZ, wtlo + 1 * WSZ);
    wtsplit_kernel<<<wtgrid, wtblk>>>(Wv, wthi + 2 * WSZ, wtlo + 2 * WSZ);
    wtsplit_kernel<<<wtgrid, wtblk>>>(Wo, wthi + 3 * WSZ, wtlo + 3 * WSZ);

    // projections on tensor cores (mma.sync)
    tgemm_kernel<<<tgrid, 256, TG_SMEM>>>(xnhi, xnlo, wthi + 0 * WSZ, wtlo + 0 * WSZ,
                                          nullptr, qb);
    tgemm_kernel<<<tgrid, 256, TG_SMEM>>>(xnhi, xnlo, wthi + 1 * WSZ, wtlo + 1 * WSZ,
                                          nullptr, kb);
    tgemm_kernel<<<tgrid, 256, TG_SMEM>>>(xhi,  xlo,  wthi + 2 * WSZ, wtlo + 2 * WSZ,
                                          nullptr, vb);

    qknorm_kernel<<<(MR * HH) / 8, 256>>>(qb, kb, gq, gk, gqv, gkv);
    attn_kernel<<<dim3(TT / 128, HH, BB), 256, attn_smem>>>(qb, kb, vb, gqv, gkv,
                                                            chi, clo);

    // output projection + bias
    tgemm_kernel<<<tgrid, 256, TG_SMEM>>>(chi, clo, wthi + 3 * WSZ, wtlo + 3 * WSZ,
                                          bo, out);
}

// round 9
// speedup vs baseline: 2.0596x; 1.3912x over previous
#include <cuda_runtime.h>
#include <cuda_bf16.h>
#include <math.h>
#include <stdint.h>

#define DD 1024
#define HH 16
#define HDIM 64
#define TT 2048
#define BB 2
#define MR 4096            // B*T
#define THRESHF 0.29514f
#define SHARPF 15.0f

// ---------------- mma.sync helpers (target-portable) -----------
__device__ __forceinline__ uint32_t s2u(const void* p) {
    uint32_t a;
    asm("{ .reg .u64 t; cvta.to.shared.u64 t, %1; cvt.u32.u64 %0, t; }" : "=r"(a) : "l"(p));
    return a;
}
#define SWZ(o) ((o) ^ (((o) >> 3) & 0x70))

__device__ __forceinline__ void ldsm4(uint32_t* r, uint32_t addr) {
    asm volatile("ldmatrix.sync.aligned.m8n8.x4.shared.b16 {%0,%1,%2,%3}, [%4];"
                 : "=r"(r[0]), "=r"(r[1]), "=r"(r[2]), "=r"(r[3]) : "r"(addr));
}
__device__ __forceinline__ void mma16816(float* d, const uint32_t* a, const uint32_t* b) {
    asm volatile("mma.sync.aligned.m16n8k16.row.col.f32.bf16.bf16.f32 "
                 "{%0,%1,%2,%3}, {%4,%5,%6,%7}, {%8,%9}, {%0,%1,%2,%3};"
                 : "+f"(d[0]), "+f"(d[1]), "+f"(d[2]), "+f"(d[3])
                 : "r"(a[0]), "r"(a[1]), "r"(a[2]), "r"(a[3]), "r"(b[0]), "r"(b[1]));
}
__device__ __forceinline__ uint32_t packbf(float lo, float hi) {
    uint32_t d;
    asm("cvt.rn.bf16x2.f32 %0, %1, %2;" : "=r"(d) : "f"(hi), "f"(lo));
    return d;
}
__device__ __forceinline__ void split1(float v, __nv_bfloat16& h, __nv_bfloat16& l) {
    h = __float2bfloat16(v);
    l = __float2bfloat16(v - __bfloat162float(h));
}
__device__ __forceinline__ float sgm(float s) {
    float z = (s - THRESHF) * SHARPF;
    return __fdividef(1.0f, 1.0f + __expf(-z));
}

// -------------------- scratch (device globals; no allocation) --------------------
__device__ float g_q [(size_t)MR * DD];
__device__ float g_k [(size_t)MR * DD];
__device__ float g_v [(size_t)MR * DD];
__device__ float g_gq[MR * HH];
__device__ float g_gk[MR * HH];
__device__ __nv_bfloat16 g_xnhi[(size_t)MR * DD];
__device__ __nv_bfloat16 g_xnlo[(size_t)MR * DD];
__device__ __nv_bfloat16 g_xhi [(size_t)MR * DD];
__device__ __nv_bfloat16 g_xlo [(size_t)MR * DD];
__device__ __nv_bfloat16 g_chi [(size_t)MR * DD];
__device__ __nv_bfloat16 g_clo [(size_t)MR * DD];
__device__ __nv_bfloat16 g_qhi [(size_t)MR * DD];
__device__ __nv_bfloat16 g_qlo [(size_t)MR * DD];
__device__ __nv_bfloat16 g_khi [(size_t)MR * DD];
__device__ __nv_bfloat16 g_klo [(size_t)MR * DD];
__device__ __nv_bfloat16 g_vthi[(size_t)MR * DD];   // [b][h][d][t]
__device__ __nv_bfloat16 g_vtlo[(size_t)MR * DD];
__device__ __nv_bfloat16 g_wthi[(size_t)4 * DD * DD];   // [w][n][k]
__device__ __nv_bfloat16 g_wtlo[(size_t)4 * DD * DD];

// -------------------- LayerNorm: one block per row; emits bf16 hi/lo splits ----------
__global__ __launch_bounds__(256) void ln_kernel(const float* __restrict__ x,
                                                 const float* __restrict__ w,
                                                 const float* __restrict__ bia,
                                                 __nv_bfloat16* __restrict__ yhi,
                                                 __nv_bfloat16* __restrict__ ylo) {
    int row = blockIdx.x;
    const float4* xr = (const float4*)(x + (size_t)row * DD);
    float4 v = xr[threadIdx.x];
    float sum = v.x + v.y + v.z + v.w;
    float sq  = v.x*v.x + v.y*v.y + v.z*v.z + v.w*v.w;
#pragma unroll
    for (int o = 16; o > 0; o >>= 1) {
        sum += __shfl_xor_sync(0xffffffffu, sum, o);
        sq  += __shfl_xor_sync(0xffffffffu, sq, o);
    }
    __shared__ float s1[8], s2[8];
    int wid = threadIdx.x >> 5;
    if ((threadIdx.x & 31) == 0) { s1[wid] = sum; s2[wid] = sq; }
    __syncthreads();
    sum = 0.f; sq = 0.f;
#pragma unroll
    for (int i = 0; i < 8; i++) { sum += s1[i]; sq += s2[i]; }
    float mean = sum * (1.0f / DD);
    float var  = sq * (1.0f / DD) - mean * mean;
    float inv  = rsqrtf(var + 1e-5f);
    float4 wv = ((const float4*)w)[threadIdx.x];
    float4 bv = ((const float4*)bia)[threadIdx.x];
    float o[4];
    o[0] = (v.x - mean) * inv * wv.x + bv.x;
    o[1] = (v.y - mean) * inv * wv.y + bv.y;
    o[2] = (v.z - mean) * inv * wv.z + bv.z;
    o[3] = (v.w - mean) * inv * wv.w + bv.w;
    size_t idx = (size_t)row * DD + threadIdx.x * 4;
    __nv_bfloat16 h[4], l[4];
#pragma unroll
    for (int i = 0; i < 4; i++) split1(o[i], h[i], l[i]);
    *(__nv_bfloat162*)&yhi[idx]     = __nv_bfloat162(h[0], h[1]);
    *(__nv_bfloat162*)&yhi[idx + 2] = __nv_bfloat162(h[2], h[3]);
    *(__nv_bfloat162*)&ylo[idx]     = __nv_bfloat162(l[0], l[1]);
    *(__nv_bfloat162*)&ylo[idx + 2] = __nv_bfloat162(l[2], l[3]);
}

// -------------------- elementwise split: fp32 -> hi/lo bf16 --------------------
__global__ __launch_bounds__(256) void split_kernel(const float* __restrict__ in,
                                                    __nv_bfloat16* __restrict__ hi,
                                                    __nv_bfloat16* __restrict__ lo) {
    int i = blockIdx.x * 256 + threadIdx.x;
    float4 v = ((const float4*)in)[i];
    float o[4] = {v.x, v.y, v.z, v.w};
    __nv_bfloat16 h[4], l[4];
#pragma unroll
    for (int j = 0; j < 4; j++) split1(o[j], h[j], l[j]);
    size_t idx = (size_t)i * 4;
    *(__nv_bfloat162*)&hi[idx]     = __nv_bfloat162(h[0], h[1]);
    *(__nv_bfloat162*)&hi[idx + 2] = __nv_bfloat162(h[2], h[3]);
    *(__nv_bfloat162*)&lo[idx]     = __nv_bfloat162(l[0], l[1]);
    *(__nv_bfloat162*)&lo[idx + 2] = __nv_bfloat162(l[2], l[3]);
}

// -------------------- weight transpose + split: W[k][n] -> Wt_hi/lo[n][k] ------------
__global__ void wtsplit_kernel(const float* __restrict__ W,
                               __nv_bfloat16* __restrict__ Whi,
                               __nv_bfloat16* __restrict__ Wlo) {
    __shared__ float t[32][33];
    int n0 = blockIdx.x * 32, k0 = blockIdx.y * 32;
    int tx = threadIdx.x, ty = threadIdx.y;   // (32, 8)
#pragma unroll
    for (int j = 0; j < 32; j += 8)
        t[ty + j][tx] = W[(size_t)(k0 + ty + j) * DD + n0 + tx];
    __syncthreads();
#pragma unroll
    for (int j = 0; j < 32; j += 8) {
        float v = t[tx][ty + j];
        __nv_bfloat16 h, l;
        split1(v, h, l);
        size_t o = (size_t)(n0 + ty + j) * DD + k0 + tx;
        Whi[o] = h; Wlo[o] = l;
    }
}

// -------------------- per-head V transpose + split: v[b,t,h*64+d] -> vt[b,h,d,t] -----
__global__ void vtsplit_kernel(const float* __restrict__ v,
                               __nv_bfloat16* __restrict__ vthi,
                               __nv_bfloat16* __restrict__ vtlo) {
    __shared__ float t[32][33];
    int t0 = blockIdx.x * 32, d0 = blockIdx.y * 32, b = blockIdx.z;
    int tx = threadIdx.x, ty = threadIdx.y;   // (32, 8)
#pragma unroll
    for (int j = 0; j < 32; j += 8)
        t[ty + j][tx] = v[((size_t)b * TT + t0 + ty + j) * DD + d0 + tx];
    __syncthreads();
#pragma unroll
    for (int j = 0; j < 32; j += 8) {
        int hd = d0 + ty + j;
        float val = t[tx][ty + j];
        __nv_bfloat16 h, l;
        split1(val, h, l);
        size_t o = ((size_t)b * DD + hd) * TT + t0 + tx;
        vthi[o] = h; vtlo[o] = l;
    }
}

// -------------------- mma.sync GEMM: C[M,N] = A[M,K] * Wt[N,K]^T  (split-bf16 x3) ------
#define TGA  0
#define TGAL 16384
#define TGB  32768
#define TGBL 49152
#define TG_SMEM 65536
__global__ __launch_bounds__(256) void tgemm_kernel(
    const __nv_bfloat16* __restrict__ Ahi, const __nv_bfloat16* __restrict__ Alo,
    const __nv_bfloat16* __restrict__ Bhi, const __nv_bfloat16* __restrict__ Blo,
    const float* __restrict__ bias, float* __restrict__ C) {
    extern __shared__ char smem[];
    uint32_t sb = s2u(smem);
    int tid = threadIdx.x, wid = tid >> 5, lane = tid & 31;
    int m0 = blockIdx.y << 7, n0 = blockIdx.x << 7;
    int wm = (wid & 1) << 6;      // 0 or 64
    int wn = (wid >> 1) << 5;     // 0,32,64,96

    float acc[4][4][4] = {};

    int a_row = (lane & 15);
    int a_koff = (lane >> 4) << 4;
    int b_row = ((lane >> 4) << 3) + (lane & 7);
    int b_koff = ((lane >> 3) & 1) << 4;

    for (int kc = 0; kc < 16; kc++) {
        int k0 = kc << 6;
        __syncthreads();
        for (int u = tid; u < 1024; u += 256) {
            int r = u >> 3, s = u & 7;
            uint32_t doff = SWZ((r << 7) + (s << 4));
            size_t ga = ((size_t)(m0 + r) << 10) + k0 + (s << 3);
            size_t gb = ((size_t)(n0 + r) << 10) + k0 + (s << 3);
            *(uint4*)(smem + TGA  + doff) = *(const uint4*)(Ahi + ga);
            *(uint4*)(smem + TGAL + doff) = *(const uint4*)(Alo + ga);
            *(uint4*)(smem + TGB  + doff) = *(const uint4*)(Bhi + gb);
            *(uint4*)(smem + TGBL + doff) = *(const uint4*)(Blo + gb);
        }
        __syncthreads();

#pragma unroll
        for (int ks = 0; ks < 4; ks++) {
            int kb = ks << 5;
            uint32_t af[4][4];
            uint32_t bh[4][2], bl[4][2];
#pragma unroll
            for (int nt2 = 0; nt2 < 2; nt2++) {
                int nrow = wn + (nt2 << 4) + b_row;
                uint32_t off = SWZ((nrow << 7) + kb + b_koff);
                uint32_t r4[4];
                ldsm4(r4, sb + TGB + off);
                bh[nt2 * 2][0] = r4[0]; bh[nt2 * 2][1] = r4[1];
                bh[nt2 * 2 + 1][0] = r4[2]; bh[nt2 * 2 + 1][1] = r4[3];
                ldsm4(r4, sb + TGBL + off);
                bl[nt2 * 2][0] = r4[0]; bl[nt2 * 2][1] = r4[1];
                bl[nt2 * 2 + 1][0] = r4[2]; bl[nt2 * 2 + 1][1] = r4[3];
            }
#pragma unroll
            for (int mt = 0; mt < 4; mt++) {
                int row = wm + (mt << 4) + a_row;
                ldsm4(af[mt], sb + TGA + SWZ((row << 7) + kb + a_koff));
            }
#pragma unroll
            for (int mt = 0; mt < 4; mt++)
#pragma unroll
                for (int nt = 0; nt < 4; nt++) {
                    mma16816(acc[mt][nt], af[mt], bh[nt]);
                    mma16816(acc[mt][nt], af[mt], bl[nt]);
                }
#pragma unroll
            for (int mt = 0; mt < 4; mt++) {
                int row = wm + (mt << 4) + a_row;
                ldsm4(af[mt], sb + TGAL + SWZ((row << 7) + kb + a_koff));
            }
#pragma unroll
            for (int mt = 0; mt < 4; mt++)
#pragma unroll
                for (int nt = 0; nt < 4; nt++)
                    mma16816(acc[mt][nt], af[mt], bh[nt]);
        }
    }

    int g = lane >> 2, t4 = lane & 3;
#pragma unroll
    for (int mt = 0; mt < 4; mt++) {
#pragma unroll
        for (int nt = 0; nt < 4; nt++) {
            int col = n0 + wn + (nt << 3) + (t4 << 1);
            float bx = 0.f, by = 0.f;
            if (bias) { float2 bv = *(const float2*)&bias[col]; bx = bv.x; by = bv.y; }
            int r0 = m0 + wm + (mt << 4) + g;
            *(float2*)&C[((size_t)r0 << 10) + col] =
                make_float2(acc[mt][nt][0] + bx, acc[mt][nt][1] + by);
            *(float2*)&C[((size_t)(r0 + 8) << 10) + col] =
                make_float2(acc[mt][nt][2] + bx, acc[mt][nt][3] + by);
        }
    }
}

// -------- L2 normalize q,k + gates; emits bf16 hi/lo splits; warp per (b,t,h) --------
__global__ __launch_bounds__(256) void qknorm_kernel(const float* __restrict__ q,
                                                     const float* __restrict__ k,
                                                     const float* __restrict__ gqw,
                                                     const float* __restrict__ gkw,
                                                     __nv_bfloat16* __restrict__ qhi,
                                                     __nv_bfloat16* __restrict__ qlo,
                                                     __nv_bfloat16* __restrict__ khi,
                                                     __nv_bfloat16* __restrict__ klo,
                                                     float* __restrict__ gateq,
                                                     float* __restrict__ gatek) {
    int r = blockIdx.x * 8 + (threadIdx.x >> 5);   // (b*T+t)*H + h
    int lane = threadIdx.x & 31;
    int bt = r >> 4, h = r & 15;
    size_t base = ((size_t)bt << 10) + (h << 6) + lane * 2;

    float2 g1 = *(const float2*)&gqw[lane * 2];
    float2 g2 = *(const float2*)&gkw[lane * 2];

    float2 qv = *(const float2*)&q[base];
    float ss = qv.x * qv.x + qv.y * qv.y;
#pragma unroll
    for (int o = 16; o > 0; o >>= 1) ss += __shfl_xor_sync(0xffffffffu, ss, o);
    float inv = 1.0f / fmaxf(sqrtf(ss), 1e-12f);
    qv.x *= inv; qv.y *= inv;
    __nv_bfloat16 hx, lx, hy, ly;
    split1(qv.x, hx, lx); split1(qv.y, hy, ly);
    *(__nv_bfloat162*)&qhi[base] = __nv_bfloat162(hx, hy);
    *(__nv_bfloat162*)&qlo[base] = __nv_bfloat162(lx, ly);
    float gd = qv.x * g1.x + qv.y * g1.y;
#pragma unroll
    for (int o = 16; o > 0; o >>= 1) gd += __shfl_xor_sync(0xffffffffu, gd, o);
    if (lane == 0) gateq[r] = gd;

    float2 kv = *(const float2*)&k[base];
    ss = kv.x * kv.x + kv.y * kv.y;
#pragma unroll
    for (int o = 16; o > 0; o >>= 1) ss += __shfl_xor_sync(0xffffffffu, ss, o);
    inv = 1.0f / fmaxf(sqrtf(ss), 1e-12f);
    kv.x *= inv; kv.y *= inv;
    split1(kv.x, hx, lx); split1(kv.y, hy, ly);
    *(__nv_bfloat162*)&khi[base] = __nv_bfloat162(hx, hy);
    *(__nv_bfloat162*)&klo[base] = __nv_bfloat162(lx, ly);
    gd = kv.x * g2.x + kv.y * g2.y;
#pragma unroll
    for (int o = 16; o > 0; o >>= 1) gd += __shfl_xor_sync(0xffffffffu, gd, o);
    if (lane == 0) gatek[r] = gd;
}

// -------------------- attention via mma.sync: 128t x 128s tiles, 8 warps --------------
#define AQH 0
#define AQL 16384
#define AKH 32768
#define AKL 49152
#define AVH 65536
#define AVL 81920
#define AGQ 98304
#define AGK 98816
#define A_SMEM 99328
__global__ __launch_bounds__(256) void attn_kernel(
    const __nv_bfloat16* __restrict__ qhi, const __nv_bfloat16* __restrict__ qlo,
    const __nv_bfloat16* __restrict__ khi, const __nv_bfloat16* __restrict__ klo,
    const __nv_bfloat16* __restrict__ vthi, const __nv_bfloat16* __restrict__ vtlo,
    const float* __restrict__ gateq, const float* __restrict__ gatek,
    __nv_bfloat16* __restrict__ ohi, __nv_bfloat16* __restrict__ olo) {
    extern __shared__ char smem[];
    uint32_t sb = s2u(smem);
    int tid = threadIdx.x, wid = tid >> 5, lane = tid & 31;
    int g = lane >> 2, t4 = lane & 3;
    int t0 = blockIdx.x << 7;
    int h = blockIdx.y, b = blockIdx.z;
    size_t headoff = (size_t)b * TT * DD + (size_t)h * HDIM;
    size_t vtoff = ((size_t)b * DD + h * HDIM) * TT;

    int a_row = lane & 15;
    int a_koff = (lane >> 4) << 4;
    int b_row = ((lane >> 4) << 3) + (lane & 7);
    int b_koff = ((lane >> 3) & 1) << 4;

    // load Q tiles (hi/lo) + gq
    for (int u = tid; u < 2048; u += 256) {
        int sp = u >> 10, r = (u >> 3) & 127, c = u & 7;
        const __nv_bfloat16* src = sp ? qlo : qhi;
        char* dst = smem + (sp ? AQL : AQH);
        *(uint4*)(dst + SWZ((r << 7) + (c << 4))) =
            *(const uint4*)(src + headoff + ((size_t)(t0 + r) << 10) + (c << 3));
    }
    if (tid < 128)
        ((float*)(smem + AGQ))[tid] = gateq[(size_t)(b * TT + t0 + tid) * HH + h];
    __syncthreads();

    // resident Q fragments (16 t-rows per warp)
    int wm16 = wid << 4;
    uint32_t aQh[4][4], aQl[4][4];
#pragma unroll
    for (int ks = 0; ks < 4; ks++) {
        uint32_t off = SWZ(((wm16 + a_row) << 7) + (ks << 5) + a_koff);
        ldsm4(aQh[ks], sb + AQH + off);
        ldsm4(aQl[ks], sb + AQL + off);
    }
    float gq0 = ((float*)(smem + AGQ))[wm16 + g];
    float gq1 = ((float*)(smem + AGQ))[wm16 + g + 8];

    float acc[8][4] = {};   // 8 d-ntiles x (c0..c3)

    for (int s0 = 0; s0 < TT; s0 += 128) {
        __syncthreads();
        // K tiles
        for (int u = tid; u < 2048; u += 256) {
            int sp = u >> 10, r = (u >> 3) & 127, c = u & 7;
            const __nv_bfloat16* src = sp ? klo : khi;
            char* dst = smem + (sp ? AKL : AKH);
            *(uint4*)(dst + SWZ((r << 7) + (c << 4))) =
                *(const uint4*)(src + headoff + ((size_t)(s0 + r) << 10) + (c << 3));
        }
        // Vt tiles (2 halves of 64 s each)
        for (int u = tid; u < 2048; u += 256) {
            int sp = u >> 10, rem = u & 1023;
            int hf = rem >> 9, d = (rem >> 3) & 63, c = rem & 7;
            const __nv_bfloat16* src = sp ? vtlo : vthi;
            char* dst = smem + (sp ? AVL : AVH) + (hf << 13);
            *(uint4*)(dst + SWZ((d << 7) + (c << 4))) =
                *(const uint4*)(src + vtoff + ((size_t)d << 11) + s0 + (hf << 6) + (c << 3));
        }
        if (tid < 128)
            ((float*)(smem + AGK))[tid] = gatek[(size_t)(b * TT + s0 + tid) * HH + h];
        __syncthreads();

        // S = Q K^T (3-term split)
        float sacc[16][4] = {};
#pragma unroll
        for (int ks = 0; ks < 4; ks++) {
            int kb = ks << 5;
#pragma unroll
            for (int nt2 = 0; nt2 < 8; nt2++) {
                uint32_t off = SWZ((((nt2 << 4) + b_row) << 7) + kb + b_koff);
                uint32_t kh[4], kl[4];
                ldsm4(kh, sb + AKH + off);
                ldsm4(kl, sb + AKL + off);
                mma16816(sacc[nt2 * 2],     aQh[ks], kh);
                mma16816(sacc[nt2 * 2 + 1], aQh[ks], kh + 2);
                mma16816(sacc[nt2 * 2],     aQh[ks], kl);
                mma16816(sacc[nt2 * 2 + 1], aQh[ks], kl + 2);
                mma16816(sacc[nt2 * 2],     aQl[ks], kh);
                mma16816(sacc[nt2 * 2 + 1], aQl[ks], kh + 2);
            }
        }

        // P = sigmoid((S-th)*sharp)*gq*gk ; pack to bf16 hi/lo A-frags; PV mma
#pragma unroll
        for (int kp = 0; kp < 8; kp++) {
            int ntA = kp * 2, ntB = kp * 2 + 1;
            float2 gkA = *(const float2*)(smem + AGK + (((ntA << 3) + (t4 << 1)) << 2));
            float2 gkB = *(const float2*)(smem + AGK + (((ntB << 3) + (t4 << 1)) << 2));
            float pa0 = sgm(sacc[ntA][0]) * (gq0 * gkA.x);
            float pa1 = sgm(sacc[ntA][1]) * (gq0 * gkA.y);
            float pa2 = sgm(sacc[ntA][2]) * (gq1 * gkA.x);
            float pa3 = sgm(sacc[ntA][3]) * (gq1 * gkA.y);
            float pb0 = sgm(sacc[ntB][0]) * (gq0 * gkB.x);
            float pb1 = sgm(sacc[ntB][1]) * (gq0 * gkB.y);
            float pb2 = sgm(sacc[ntB][2]) * (gq1 * gkB.x);
            float pb3 = sgm(sacc[ntB][3]) * (gq1 * gkB.y);

            uint32_t ph[4], pl[4];
            ph[0] = packbf(pa0, pa1); ph[1] = packbf(pa2, pa3);
            ph[2] = packbf(pb0, pb1); ph[3] = packbf(pb2, pb3);
            {
                float r0 = pa0 - __uint_as_float(ph[0] << 16);
                float r1 = pa1 - __uint_as_float(ph[0] & 0xFFFF0000u);
                pl[0] = packbf(r0, r1);
                r0 = pa2 - __uint_as_float(ph[1] << 16);
                r1 = pa3 - __uint_as_float(ph[1] & 0xFFFF0000u);
                pl[1] = packbf(r0, r1);
                r0 = pb0 - __uint_as_float(ph[2] << 16);
                r1 = pb1 - __uint_as_float(ph[2] & 0xFFFF0000u);
                pl[2] = packbf(r0, r1);
                r0 = pb2 - __uint_as_float(ph[3] << 16);
                r1 = pb3 - __uint_as_float(ph[3] & 0xFFFF0000u);
                pl[3] = packbf(r0, r1);
            }

            uint32_t vbase = ((kp >> 2) << 13) + ((kp & 3) << 5);
#pragma unroll
            for (int nt2 = 0; nt2 < 4; nt2++) {
                uint32_t off = vbase; // note: swizzle applies within 128B row
                uint32_t so = SWZ((((nt2 << 4) + b_row) << 7) + ((kp & 3) << 5) + b_koff)
                              + ((kp >> 2) << 13);
                (void)off;
                uint32_t vh[4], vl[4];
                ldsm4(vh, sb + AVH + so);
                ldsm4(vl, sb + AVL + so);
                mma16816(acc[nt2 * 2],     ph, vh);
                mma16816(acc[nt2 * 2 + 1], ph, vh + 2);
                mma16816(acc[nt2 * 2],     ph, vl);
                mma16816(acc[nt2 * 2 + 1], ph, vl + 2);
                mma16816(acc[nt2 * 2],     pl, vh);
                mma16816(acc[nt2 * 2 + 1], pl, vh + 2);
            }
        }
    }

    // epilogue: collapse -> bf16 hi/lo splits
#pragma unroll
    for (int nt = 0; nt < 8; nt++) {
        int d0 = (nt << 3) + (t4 << 1);
        int r0 = t0 + wm16 + g;
        __nv_bfloat16 h0, l0, h1, l1;
        split1(acc[nt][0], h0, l0); split1(acc[nt][1], h1, l1);
        size_t i0 = headoff + ((size_t)r0 << 10) + d0;
        *(__nv_bfloat162*)&ohi[i0] = __nv_bfloat162(h0, h1);
        *(__nv_bfloat162*)&olo[i0] = __nv_bfloat162(l0, l1);
        split1(acc[nt][2], h0, l0); split1(acc[nt][3], h1, l1);
        size_t i1 = headoff + ((size_t)(r0 + 8) << 10) + d0;
        *(__nv_bfloat162*)&ohi[i1] = __nv_bfloat162(h0, h1);
        *(__nv_bfloat162*)&olo[i1] = __nv_bfloat162(l0, l1);
    }
}

// -------------------- launch --------------------
extern "C" void kernel_launch(void* const* d_in, const int* in_sizes, int n_in,
                              void* d_out, int out_size) {
    (void)in_sizes; (void)n_in; (void)out_size;
    const float* x   = (const float*)d_in[0];
    const float* Wq  = (const float*)d_in[1];
    const float* Wk  = (const float*)d_in[2];
    const float* Wv  = (const float*)d_in[3];
    const float* gq  = (const float*)d_in[4];
    const float* gk  = (const float*)d_in[5];
    const float* Wo  = (const float*)d_in[6];
    const float* bo  = (const float*)d_in[7];
    const float* lnw = (const float*)d_in[8];
    const float* lnb = (const float*)d_in[9];
    float* out = (float*)d_out;

    float *qb, *kb, *vb, *gqv, *gkv;
    __nv_bfloat16 *xnhi, *xnlo, *xhi, *xlo, *chi, *clo, *wthi, *wtlo;
    __nv_bfloat16 *qhi, *qlo, *khi, *klo, *vthi, *vtlo;
    cudaGetSymbolAddress((void**)&qb,   g_q);
    cudaGetSymbolAddress((void**)&kb,   g_k);
    cudaGetSymbolAddress((void**)&vb,   g_v);
    cudaGetSymbolAddress((void**)&gqv,  g_gq);
    cudaGetSymbolAddress((void**)&gkv,  g_gk);
    cudaGetSymbolAddress((void**)&xnhi, g_xnhi);
    cudaGetSymbolAddress((void**)&xnlo, g_xnlo);
    cudaGetSymbolAddress((void**)&xhi,  g_xhi);
    cudaGetSymbolAddress((void**)&xlo,  g_xlo);
    cudaGetSymbolAddress((void**)&chi,  g_chi);
    cudaGetSymbolAddress((void**)&clo,  g_clo);
    cudaGetSymbolAddress((void**)&qhi,  g_qhi);
    cudaGetSymbolAddress((void**)&qlo,  g_qlo);
    cudaGetSymbolAddress((void**)&khi,  g_khi);
    cudaGetSymbolAddress((void**)&klo,  g_klo);
    cudaGetSymbolAddress((void**)&vthi, g_vthi);
    cudaGetSymbolAddress((void**)&vtlo, g_vtlo);
    cudaGetSymbolAddress((void**)&wthi, g_wthi);
    cudaGetSymbolAddress((void**)&wtlo, g_wtlo);

    const size_t WSZ = (size_t)DD * DD;

    cudaFuncSetAttribute(attn_kernel, cudaFuncAttributeMaxDynamicSharedMemorySize,
                         A_SMEM);
    cudaFuncSetAttribute(tgemm_kernel, cudaFuncAttributeMaxDynamicSharedMemorySize,
                         TG_SMEM);

    dim3 tgrid(DD / 128, MR / 128);       // (8, 32)
    dim3 wtgrid(DD / 32, DD / 32);
    dim3 wtblk(32, 8);
    dim3 vtgrid(TT / 32, DD / 32, BB);

    // prep
    ln_kernel<<<MR, 256>>>(x, lnw, lnb, xnhi, xnlo);
    split_kernel<<<(MR * DD) / (256 * 4), 256>>>(x, xhi, xlo);
    wtsplit_kernel<<<wtgrid, wtblk>>>(Wq, wthi + 0 * WSZ, wtlo + 0 * WSZ);
    wtsplit_kernel<<<wtgrid, wtblk>>>(Wk, wthi + 1 * WSZ, wtlo + 1 * WSZ);
    wtsplit_kernel<<<wtgrid, wtblk>>>(Wv, wthi + 2 * WSZ, wtlo + 2 * WSZ);
    wtsplit_kernel<<<wtgrid, wtblk>>>(Wo, wthi + 3 * WSZ, wtlo + 3 * WSZ);

    // projections on tensor cores
    tgemm_kernel<<<tgrid, 256, TG_SMEM>>>(xnhi, xnlo, wthi + 0 * WSZ, wtlo + 0 * WSZ,
                                          nullptr, qb);
    tgemm_kernel<<<tgrid, 256, TG_SMEM>>>(xnhi, xnlo, wthi + 1 * WSZ, wtlo + 1 * WSZ,
                                          nullptr, kb);
    tgemm_kernel<<<tgrid, 256, TG_SMEM>>>(xhi,  xlo,  wthi + 2 * WSZ, wtlo + 2 * WSZ,
                                          nullptr, vb);

    qknorm_kernel<<<(MR * HH) / 8, 256>>>(qb, kb, gq, gk, qhi, qlo, khi, klo, gqv, gkv);
    vtsplit_kernel<<<vtgrid, wtblk>>>(vb, vthi, vtlo);

    attn_kernel<<<dim3(TT / 128, HH, BB), 256, A_SMEM>>>(
        qhi, qlo, khi, klo, vthi, vtlo, gqv, gkv, chi, clo);

    // output projection + bias
    tgemm_kernel<<<tgrid, 256, TG_SMEM>>>(chi, clo, wthi + 3 * WSZ, wtlo + 3 * WSZ,
                                          bo, out);
}

// round 10
// speedup vs baseline: 3.1578x; 1.5332x over previous
#include <cuda_runtime.h>
#include <cuda_bf16.h>
#include <math.h>
#include <stdint.h>

#define DD 1024
#define HH 16
#define HDIM 64
#define TT 2048
#define BB 2
#define MR 4096            // B*T
#define THRESHF 0.29514f
#define SHARPF 15.0f

// ---------------- mma.sync / cp.async helpers (target-portable) -----------
__device__ __forceinline__ uint32_t s2u(const void* p) {
    uint32_t a;
    asm("{ .reg .u64 t; cvta.to.shared.u64 t, %1; cvt.u32.u64 %0, t; }" : "=r"(a) : "l"(p));
    return a;
}
#define SWZ(o) ((o) ^ (((o) >> 3) & 0x70))

__device__ __forceinline__ void ldsm4(uint32_t* r, uint32_t addr) {
    asm volatile("ldmatrix.sync.aligned.m8n8.x4.shared.b16 {%0,%1,%2,%3}, [%4];"
                 : "=r"(r[0]), "=r"(r[1]), "=r"(r[2]), "=r"(r[3]) : "r"(addr));
}
__device__ __forceinline__ void mma16816(float* d, const uint32_t* a, const uint32_t* b) {
    asm volatile("mma.sync.aligned.m16n8k16.row.col.f32.bf16.bf16.f32 "
                 "{%0,%1,%2,%3}, {%4,%5,%6,%7}, {%8,%9}, {%0,%1,%2,%3};"
                 : "+f"(d[0]), "+f"(d[1]), "+f"(d[2]), "+f"(d[3])
                 : "r"(a[0]), "r"(a[1]), "r"(a[2]), "r"(a[3]), "r"(b[0]), "r"(b[1]));
}
__device__ __forceinline__ void cpasync16(uint32_t dst, const void* src) {
    asm volatile("cp.async.cg.shared.global [%0], [%1], 16;" :: "r"(dst), "l"(src));
}
#define CP_COMMIT() asm volatile("cp.async.commit_group;" ::: "memory")
#define CP_WAIT1()  asm volatile("cp.async.wait_group 1;" ::: "memory")
#define CP_WAIT0()  asm volatile("cp.async.wait_group 0;" ::: "memory")

__device__ __forceinline__ uint32_t packbf(float lo, float hi) {
    uint32_t d;
    asm("cvt.rn.bf16x2.f32 %0, %1, %2;" : "=r"(d) : "f"(hi), "f"(lo));
    return d;
}
__device__ __forceinline__ void split1(float v, __nv_bfloat16& h, __nv_bfloat16& l) {
    h = __float2bfloat16(v);
    l = __float2bfloat16(v - __bfloat162float(h));
}
__device__ __forceinline__ float sgm(float s) {
    float z = (s - THRESHF) * SHARPF;
    return __fdividef(1.0f, 1.0f + __expf(-z));
}

// -------------------- scratch (device globals; no allocation) --------------------
__device__ float g_q [(size_t)MR * DD];
__device__ float g_k [(size_t)MR * DD];
__device__ float g_v [(size_t)MR * DD];
__device__ float g_gq[MR * HH];   // layout [b][h][t]
__device__ float g_gk[MR * HH];   // layout [b][h][t]
__device__ __nv_bfloat16 g_xnhi[(size_t)MR * DD];
__device__ __nv_bfloat16 g_xnlo[(size_t)MR * DD];
__device__ __nv_bfloat16 g_xhi [(size_t)MR * DD];
__device__ __nv_bfloat16 g_xlo [(size_t)MR * DD];
__device__ __nv_bfloat16 g_chi [(size_t)MR * DD];
__device__ __nv_bfloat16 g_clo [(size_t)MR * DD];
__device__ __nv_bfloat16 g_qhi [(size_t)MR * DD];
__device__ __nv_bfloat16 g_qlo [(size_t)MR * DD];
__device__ __nv_bfloat16 g_khi [(size_t)MR * DD];
__device__ __nv_bfloat16 g_klo [(size_t)MR * DD];
__device__ __nv_bfloat16 g_vthi[(size_t)MR * DD];   // [b][h][d][t]
__device__ __nv_bfloat16 g_vtlo[(size_t)MR * DD];
__device__ __nv_bfloat16 g_wthi[(size_t)4 * DD * DD];   // [w][n][k]
__device__ __nv_bfloat16 g_wtlo[(size_t)4 * DD * DD];

// -------------------- LayerNorm: one block per row; emits bf16 hi/lo splits ----------
__global__ __launch_bounds__(256) void ln_kernel(const float* __restrict__ x,
                                                 const float* __restrict__ w,
                                                 const float* __restrict__ bia,
                                                 __nv_bfloat16* __restrict__ yhi,
                                                 __nv_bfloat16* __restrict__ ylo) {
    int row = blockIdx.x;
    const float4* xr = (const float4*)(x + (size_t)row * DD);
    float4 v = xr[threadIdx.x];
    float sum = v.x + v.y + v.z + v.w;
    float sq  = v.x*v.x + v.y*v.y + v.z*v.z + v.w*v.w;
#pragma unroll
    for (int o = 16; o > 0; o >>= 1) {
        sum += __shfl_xor_sync(0xffffffffu, sum, o);
        sq  += __shfl_xor_sync(0xffffffffu, sq, o);
    }
    __shared__ float s1[8], s2[8];
    int wid = threadIdx.x >> 5;
    if ((threadIdx.x & 31) == 0) { s1[wid] = sum; s2[wid] = sq; }
    __syncthreads();
    sum = 0.f; sq = 0.f;
#pragma unroll
    for (int i = 0; i < 8; i++) { sum += s1[i]; sq += s2[i]; }
    float mean = sum * (1.0f / DD);
    float var  = sq * (1.0f / DD) - mean * mean;
    float inv  = rsqrtf(var + 1e-5f);
    float4 wv = ((const float4*)w)[threadIdx.x];
    float4 bv = ((const float4*)bia)[threadIdx.x];
    float o[4];
    o[0] = (v.x - mean) * inv * wv.x + bv.x;
    o[1] = (v.y - mean) * inv * wv.y + bv.y;
    o[2] = (v.z - mean) * inv * wv.z + bv.z;
    o[3] = (v.w - mean) * inv * wv.w + bv.w;
    size_t idx = (size_t)row * DD + threadIdx.x * 4;
    __nv_bfloat16 h[4], l[4];
#pragma unroll
    for (int i = 0; i < 4; i++) split1(o[i], h[i], l[i]);
    *(__nv_bfloat162*)&yhi[idx]     = __nv_bfloat162(h[0], h[1]);
    *(__nv_bfloat162*)&yhi[idx + 2] = __nv_bfloat162(h[2], h[3]);
    *(__nv_bfloat162*)&ylo[idx]     = __nv_bfloat162(l[0], l[1]);
    *(__nv_bfloat162*)&ylo[idx + 2] = __nv_bfloat162(l[2], l[3]);
}

// -------------------- elementwise split: fp32 -> hi/lo bf16 --------------------
__global__ __launch_bounds__(256) void split_kernel(const float* __restrict__ in,
                                                    __nv_bfloat16* __restrict__ hi,
                                                    __nv_bfloat16* __restrict__ lo) {
    int i = blockIdx.x * 256 + threadIdx.x;
    float4 v = ((const float4*)in)[i];
    float o[4] = {v.x, v.y, v.z, v.w};
    __nv_bfloat16 h[4], l[4];
#pragma unroll
    for (int j = 0; j < 4; j++) split1(o[j], h[j], l[j]);
    size_t idx = (size_t)i * 4;
    *(__nv_bfloat162*)&hi[idx]     = __nv_bfloat162(h[0], h[1]);
    *(__nv_bfloat162*)&hi[idx + 2] = __nv_bfloat162(h[2], h[3]);
    *(__nv_bfloat162*)&lo[idx]     = __nv_bfloat162(l[0], l[1]);
    *(__nv_bfloat162*)&lo[idx + 2] = __nv_bfloat162(l[2], l[3]);
}

// ------------- weight transpose + split x4: W[k][n] -> Wt_hi/lo[w][n][k] -------------
__global__ void wtsplit4_kernel(const float* __restrict__ W0, const float* __restrict__ W1,
                                const float* __restrict__ W2, const float* __restrict__ W3,
                                __nv_bfloat16* __restrict__ Whi,
                                __nv_bfloat16* __restrict__ Wlo) {
    __shared__ float t[32][33];
    int wz = blockIdx.z;
    const float* W = wz == 0 ? W0 : wz == 1 ? W1 : wz == 2 ? W2 : W3;
    __nv_bfloat16* wh = Whi + (size_t)wz * DD * DD;
    __nv_bfloat16* wl = Wlo + (size_t)wz * DD * DD;
    int n0 = blockIdx.x * 32, k0 = blockIdx.y * 32;
    int tx = threadIdx.x, ty = threadIdx.y;   // (32, 8)
#pragma unroll
    for (int j = 0; j < 32; j += 8)
        t[ty + j][tx] = W[(size_t)(k0 + ty + j) * DD + n0 + tx];
    __syncthreads();
#pragma unroll
    for (int j = 0; j < 32; j += 8) {
        float v = t[tx][ty + j];
        __nv_bfloat16 h, l;
        split1(v, h, l);
        size_t o = (size_t)(n0 + ty + j) * DD + k0 + tx;
        wh[o] = h; wl[o] = l;
    }
}

// -------------------- per-head V transpose + split: v[b,t,h*64+d] -> vt[b,h,d,t] -----
__global__ void vtsplit_kernel(const float* __restrict__ v,
                               __nv_bfloat16* __restrict__ vthi,
                               __nv_bfloat16* __restrict__ vtlo) {
    __shared__ float t[32][33];
    int t0 = blockIdx.x * 32, d0 = blockIdx.y * 32, b = blockIdx.z;
    int tx = threadIdx.x, ty = threadIdx.y;   // (32, 8)
#pragma unroll
    for (int j = 0; j < 32; j += 8)
        t[ty + j][tx] = v[((size_t)b * TT + t0 + ty + j) * DD + d0 + tx];
    __syncthreads();
#pragma unroll
    for (int j = 0; j < 32; j += 8) {
        int hd = d0 + ty + j;
        float val = t[tx][ty + j];
        __nv_bfloat16 h, l;
        split1(val, h, l);
        size_t o = ((size_t)b * DD + hd) * TT + t0 + tx;
        vthi[o] = h; vtlo[o] = l;
    }
}

// -------------------- mma.sync GEMM with 2-stage cp.async pipeline -------------------
// C[M,N] = A[M,K] * Wt[N,K]^T  (split-bf16 x3). 128x128 tile, BK=64.
// Stage layout (65536 B): Ahi 0, Alo 16384, Bhi 32768, Blo 49152.
#define TG_STG 65536
#define TG_SMEM (2 * TG_STG)
__device__ __forceinline__ void tg_load_stage(
    uint32_t st, const __nv_bfloat16* Ahi, const __nv_bfloat16* Alo,
    const __nv_bfloat16* Bhi, const __nv_bfloat16* Blo,
    int m0, int n0, int k0, int tid) {
#pragma unroll
    for (int u = tid; u < 1024; u += 256) {
        int r = u >> 3, s = u & 7;
        uint32_t doff = SWZ((r << 7) + (s << 4));
        size_t ga = ((size_t)(m0 + r) << 10) + k0 + (s << 3);
        size_t gb = ((size_t)(n0 + r) << 10) + k0 + (s << 3);
        cpasync16(st + doff,         Ahi + ga);
        cpasync16(st + 16384 + doff, Alo + ga);
        cpasync16(st + 32768 + doff, Bhi + gb);
        cpasync16(st + 49152 + doff, Blo + gb);
    }
}
__global__ __launch_bounds__(256) void tgemm_kernel(
    const __nv_bfloat16* __restrict__ Ahi, const __nv_bfloat16* __restrict__ Alo,
    const __nv_bfloat16* __restrict__ Bhi, const __nv_bfloat16* __restrict__ Blo,
    const float* __restrict__ bias, float* __restrict__ C) {
    extern __shared__ char smem[];
    uint32_t sb = s2u(smem);
    int tid = threadIdx.x, wid = tid >> 5, lane = tid & 31;
    int m0 = blockIdx.y << 7, n0 = blockIdx.x << 7;
    int wm = (wid & 1) << 6;
    int wn = (wid >> 1) << 5;

    float acc[4][4][4] = {};

    int a_row = (lane & 15);
    int a_koff = (lane >> 4) << 4;
    int b_row = ((lane >> 4) << 3) + (lane & 7);
    int b_koff = ((lane >> 3) & 1) << 4;

    tg_load_stage(sb, Ahi, Alo, Bhi, Blo, m0, n0, 0, tid);
    CP_COMMIT();

    for (int kc = 0; kc < 16; kc++) {
        if (kc < 15) {
            tg_load_stage(sb + ((kc + 1) & 1) * TG_STG, Ahi, Alo, Bhi, Blo,
                          m0, n0, (kc + 1) << 6, tid);
            CP_COMMIT();
            CP_WAIT1();
        } else {
            CP_WAIT0();
        }
        __syncthreads();
        uint32_t st = sb + (kc & 1) * TG_STG;

#pragma unroll
        for (int ks = 0; ks < 4; ks++) {
            int kb = ks << 5;
            uint32_t af[4][4];
            uint32_t bh[4][2], bl[4][2];
#pragma unroll
            for (int nt2 = 0; nt2 < 2; nt2++) {
                int nrow = wn + (nt2 << 4) + b_row;
                uint32_t off = SWZ((nrow << 7) + kb + b_koff);
                uint32_t r4[4];
                ldsm4(r4, st + 32768 + off);
                bh[nt2 * 2][0] = r4[0]; bh[nt2 * 2][1] = r4[1];
                bh[nt2 * 2 + 1][0] = r4[2]; bh[nt2 * 2 + 1][1] = r4[3];
                ldsm4(r4, st + 49152 + off);
                bl[nt2 * 2][0] = r4[0]; bl[nt2 * 2][1] = r4[1];
                bl[nt2 * 2 + 1][0] = r4[2]; bl[nt2 * 2 + 1][1] = r4[3];
            }
#pragma unroll
            for (int mt = 0; mt < 4; mt++) {
                int row = wm + (mt << 4) + a_row;
                ldsm4(af[mt], st + SWZ((row << 7) + kb + a_koff));
            }
#pragma unroll
            for (int mt = 0; mt < 4; mt++)
#pragma unroll
                for (int nt = 0; nt < 4; nt++) {
                    mma16816(acc[mt][nt], af[mt], bh[nt]);
                    mma16816(acc[mt][nt], af[mt], bl[nt]);
                }
#pragma unroll
            for (int mt = 0; mt < 4; mt++) {
                int row = wm + (mt << 4) + a_row;
                ldsm4(af[mt], st + 16384 + SWZ((row << 7) + kb + a_koff));
            }
#pragma unroll
            for (int mt = 0; mt < 4; mt++)
#pragma unroll
                for (int nt = 0; nt < 4; nt++)
                    mma16816(acc[mt][nt], af[mt], bh[nt]);
        }
        __syncthreads();
    }

    int g = lane >> 2, t4 = lane & 3;
#pragma unroll
    for (int mt = 0; mt < 4; mt++) {
#pragma unroll
        for (int nt = 0; nt < 4; nt++) {
            int col = n0 + wn + (nt << 3) + (t4 << 1);
            float bx = 0.f, by = 0.f;
            if (bias) { float2 bv = *(const float2*)&bias[col]; bx = bv.x; by = bv.y; }
            int r0 = m0 + wm + (mt << 4) + g;
            *(float2*)&C[((size_t)r0 << 10) + col] =
                make_float2(acc[mt][nt][0] + bx, acc[mt][nt][1] + by);
            *(float2*)&C[((size_t)(r0 + 8) << 10) + col] =
                make_float2(acc[mt][nt][2] + bx, acc[mt][nt][3] + by);
        }
    }
}

// -------- L2 normalize q,k + gates (transposed [b,h,t]); warp per (b,t,h) --------
__global__ __launch_bounds__(256) void qknorm_kernel(const float* __restrict__ q,
                                                     const float* __restrict__ k,
                                                     const float* __restrict__ gqw,
                                                     const float* __restrict__ gkw,
                                                     __nv_bfloat16* __restrict__ qhi,
                                                     __nv_bfloat16* __restrict__ qlo,
                                                     __nv_bfloat16* __restrict__ khi,
                                                     __nv_bfloat16* __restrict__ klo,
                                                     float* __restrict__ gateq,
                                                     float* __restrict__ gatek) {
    int r = blockIdx.x * 8 + (threadIdx.x >> 5);   // (b*T+t)*H + h
    int lane = threadIdx.x & 31;
    int bt = r >> 4, h = r & 15;
    int b = bt >> 11, t = bt & 2047;
    size_t base = ((size_t)bt << 10) + (h << 6) + lane * 2;
    size_t gidx = (((size_t)(b << 4) + h) << 11) + t;

    float2 g1 = *(const float2*)&gqw[lane * 2];
    float2 g2 = *(const float2*)&gkw[lane * 2];

    float2 qv = *(const float2*)&q[base];
    float ss = qv.x * qv.x + qv.y * qv.y;
#pragma unroll
    for (int o = 16; o > 0; o >>= 1) ss += __shfl_xor_sync(0xffffffffu, ss, o);
    float inv = 1.0f / fmaxf(sqrtf(ss), 1e-12f);
    qv.x *= inv; qv.y *= inv;
    __nv_bfloat16 hx, lx, hy, ly;
    split1(qv.x, hx, lx); split1(qv.y, hy, ly);
    *(__nv_bfloat162*)&qhi[base] = __nv_bfloat162(hx, hy);
    *(__nv_bfloat162*)&qlo[base] = __nv_bfloat162(lx, ly);
    float gd = qv.x * g1.x + qv.y * g1.y;
#pragma unroll
    for (int o = 16; o > 0; o >>= 1) gd += __shfl_xor_sync(0xffffffffu, gd, o);
    if (lane == 0) gateq[gidx] = gd;

    float2 kv = *(const float2*)&k[base];
    ss = kv.x * kv.x + kv.y * kv.y;
#pragma unroll
    for (int o = 16; o > 0; o >>= 1) ss += __shfl_xor_sync(0xffffffffu, ss, o);
    inv = 1.0f / fmaxf(sqrtf(ss), 1e-12f);
    kv.x *= inv; kv.y *= inv;
    split1(kv.x, hx, lx); split1(kv.y, hy, ly);
    *(__nv_bfloat162*)&khi[base] = __nv_bfloat162(hx, hy);
    *(__nv_bfloat162*)&klo[base] = __nv_bfloat162(lx, ly);
    gd = kv.x * g2.x + kv.y * g2.y;
#pragma unroll
    for (int o = 16; o > 0; o >>= 1) gd += __shfl_xor_sync(0xffffffffu, gd, o);
    if (lane == 0) gatek[gidx] = gd;
}

// ------------- attention via mma.sync + 2-stage cp.async pipeline -------------
// Smem: Q hi 0, Q lo 16384; stages at 32768 + s*66048
//   (stage: Khi 0, Klo 16384, Vhi 32768, Vlo 49152, gk 65536..66047); gq at 164864.
#define AT_STG0 32768
#define AT_STGS 66048
#define AT_GQ   164864
#define A_SMEM  165376
__device__ __forceinline__ void at_load_stage(
    uint32_t st, const __nv_bfloat16* khi, const __nv_bfloat16* klo,
    const __nv_bfloat16* vthi, const __nv_bfloat16* vtlo,
    const float* gatek, size_t headoff, size_t vtoff, size_t gkoff,
    int s0, int tid) {
#pragma unroll
    for (int u = tid; u < 2048; u += 256) {   // K hi/lo
        int sp = u >> 10, r = (u >> 3) & 127, c = u & 7;
        const __nv_bfloat16* src = sp ? klo : khi;
        uint32_t dst = st + (sp ? 16384 : 0) + SWZ((r << 7) + (c << 4));
        cpasync16(dst, src + headoff + ((size_t)(s0 + r) << 10) + (c << 3));
    }
#pragma unroll
    for (int u = tid; u < 2048; u += 256) {   // V hi/lo (two 64-s halves)
        int sp = u >> 10, rem = u & 1023;
        int hf = rem >> 9, d = (rem >> 3) & 63, c = rem & 7;
        const __nv_bfloat16* src = sp ? vtlo : vthi;
        uint32_t dst = st + (sp ? 49152 : 32768) + (hf << 13) + SWZ((d << 7) + (c << 4));
        cpasync16(dst, src + vtoff + ((size_t)d << 11) + s0 + (hf << 6) + (c << 3));
    }
    if (tid < 32)
        cpasync16(st + 65536 + (tid << 4), gatek + gkoff + s0 + (tid << 2));
}
__global__ __launch_bounds__(256) void attn_kernel(
    const __nv_bfloat16* __restrict__ qhi, const __nv_bfloat16* __restrict__ qlo,
    const __nv_bfloat16* __restrict__ khi, const __nv_bfloat16* __restrict__ klo,
    const __nv_bfloat16* __restrict__ vthi, const __nv_bfloat16* __restrict__ vtlo,
    const float* __restrict__ gateq, const float* __restrict__ gatek,
    __nv_bfloat16* __restrict__ ohi, __nv_bfloat16* __restrict__ olo) {
    extern __shared__ char smem[];
    uint32_t sb = s2u(smem);
    int tid = threadIdx.x, wid = tid >> 5, lane = tid & 31;
    int g = lane >> 2, t4 = lane & 3;
    int t0 = blockIdx.x << 7;
    int h = blockIdx.y, b = blockIdx.z;
    size_t headoff = (size_t)b * TT * DD + (size_t)h * HDIM;
    size_t vtoff = ((size_t)b * DD + h * HDIM) * TT;
    size_t goff = ((size_t)(b * HH + h)) << 11;

    int a_row = lane & 15;
    int a_koff = (lane >> 4) << 4;
    int b_row = ((lane >> 4) << 3) + (lane & 7);
    int b_koff = ((lane >> 3) & 1) << 4;

    // Q tiles (regular loads) + gq + first K/V stage (cp.async)
    for (int u = tid; u < 2048; u += 256) {
        int sp = u >> 10, r = (u >> 3) & 127, c = u & 7;
        const __nv_bfloat16* src = sp ? qlo : qhi;
        char* dst = smem + (sp ? 16384 : 0);
        *(uint4*)(dst + SWZ((r << 7) + (c << 4))) =
            *(const uint4*)(src + headoff + ((size_t)(t0 + r) << 10) + (c << 3));
    }
    if (tid < 32) {
        float4 gv = *(const float4*)&gateq[goff + t0 + (tid << 2)];
        *(float4*)(smem + AT_GQ + (tid << 4)) = gv;
    }
    at_load_stage(sb + AT_STG0, khi, klo, vthi, vtlo, gatek,
                  headoff, vtoff, goff, 0, tid);
    CP_COMMIT();
    __syncthreads();

    // resident Q fragments (16 t-rows per warp)
    int wm16 = wid << 4;
    uint32_t aQh[4][4], aQl[4][4];
#pragma unroll
    for (int ks = 0; ks < 4; ks++) {
        uint32_t off = SWZ(((wm16 + a_row) << 7) + (ks << 5) + a_koff);
        ldsm4(aQh[ks], sb + off);
        ldsm4(aQl[ks], sb + 16384 + off);
    }
    float gq0 = ((float*)(smem + AT_GQ))[wm16 + g];
    float gq1 = ((float*)(smem + AT_GQ))[wm16 + g + 8];

    float acc[8][4] = {};

    for (int it = 0; it < 16; it++) {
        if (it < 15) {
            at_load_stage(sb + AT_STG0 + ((it + 1) & 1) * AT_STGS, khi, klo, vthi, vtlo,
                          gatek, headoff, vtoff, goff, (it + 1) << 7, tid);
            CP_COMMIT();
            CP_WAIT1();
        } else {
            CP_WAIT0();
        }
        __syncthreads();
        uint32_t stoff = AT_STG0 + (it & 1) * AT_STGS;
        uint32_t st = sb + stoff;

        // S = Q K^T (3-term split)
        float sacc[16][4] = {};
#pragma unroll
        for (int ks = 0; ks < 4; ks++) {
            int kb = ks << 5;
#pragma unroll
            for (int nt2 = 0; nt2 < 8; nt2++) {
                uint32_t off = SWZ((((nt2 << 4) + b_row) << 7) + kb + b_koff);
                uint32_t kh[4], kl[4];
                ldsm4(kh, st + off);
                ldsm4(kl, st + 16384 + off);
                mma16816(sacc[nt2 * 2],     aQh[ks], kh);
                mma16816(sacc[nt2 * 2 + 1], aQh[ks], kh + 2);
                mma16816(sacc[nt2 * 2],     aQh[ks], kl);
                mma16816(sacc[nt2 * 2 + 1], aQh[ks], kl + 2);
                mma16816(sacc[nt2 * 2],     aQl[ks], kh);
                mma16816(sacc[nt2 * 2 + 1], aQl[ks], kh + 2);
            }
        }

        // P = sigmoid((S-th)*sharp)*gq*gk ; pack to bf16 hi/lo A-frags; PV mma
#pragma unroll
        for (int kp = 0; kp < 8; kp++) {
            int ntA = kp * 2, ntB = kp * 2 + 1;
            float2 gkA = *(const float2*)(smem + stoff + 65536 +
                                          (((ntA << 3) + (t4 << 1)) << 2));
            float2 gkB = *(const float2*)(smem + stoff + 65536 +
                                          (((ntB << 3) + (t4 << 1)) << 2));
            float pa0 = sgm(sacc[ntA][0]) * (gq0 * gkA.x);
            float pa1 = sgm(sacc[ntA][1]) * (gq0 * gkA.y);
            float pa2 = sgm(sacc[ntA][2]) * (gq1 * gkA.x);
            float pa3 = sgm(sacc[ntA][3]) * (gq1 * gkA.y);
            float pb0 = sgm(sacc[ntB][0]) * (gq0 * gkB.x);
            float pb1 = sgm(sacc[ntB][1]) * (gq0 * gkB.y);
            float pb2 = sgm(sacc[ntB][2]) * (gq1 * gkB.x);
            float pb3 = sgm(sacc[ntB][3]) * (gq1 * gkB.y);

            uint32_t ph[4], pl[4];
            ph[0] = packbf(pa0, pa1); ph[1] = packbf(pa2, pa3);
            ph[2] = packbf(pb0, pb1); ph[3] = packbf(pb2, pb3);
            {
                float r0 = pa0 - __uint_as_float(ph[0] << 16);
                float r1 = pa1 - __uint_as_float(ph[0] & 0xFFFF0000u);
                pl[0] = packbf(r0, r1);
                r0 = pa2 - __uint_as_float(ph[1] << 16);
                r1 = pa3 - __uint_as_float(ph[1] & 0xFFFF0000u);
                pl[1] = packbf(r0, r1);
                r0 = pb0 - __uint_as_float(ph[2] << 16);
                r1 = pb1 - __uint_as_float(ph[2] & 0xFFFF0000u);
                pl[2] = packbf(r0, r1);
                r0 = pb2 - __uint_as_float(ph[3] << 16);
                r1 = pb3 - __uint_as_float(ph[3] & 0xFFFF0000u);
                pl[3] = packbf(r0, r1);
            }

#pragma unroll
            for (int nt2 = 0; nt2 < 4; nt2++) {
                uint32_t so = SWZ((((nt2 << 4) + b_row) << 7) + ((kp & 3) << 5) + b_koff)
                              + ((kp >> 2) << 13);
                uint32_t vh[4], vl[4];
                ldsm4(vh, st + 32768 + so);
                ldsm4(vl, st + 49152 + so);
                mma16816(acc[nt2 * 2],     ph, vh);
                mma16816(acc[nt2 * 2 + 1], ph, vh + 2);
                mma16816(acc[nt2 * 2],     ph, vl);
                mma16816(acc[nt2 * 2 + 1], ph, vl + 2);
                mma16816(acc[nt2 * 2],     pl, vh);
                mma16816(acc[nt2 * 2 + 1], pl, vh + 2);
            }
        }
        __syncthreads();
    }

    // epilogue: collapse -> bf16 hi/lo splits
#pragma unroll
    for (int nt = 0; nt < 8; nt++) {
        int d0 = (nt << 3) + (t4 << 1);
        int r0 = t0 + wm16 + g;
        __nv_bfloat16 h0, l0, h1, l1;
        split1(acc[nt][0], h0, l0); split1(acc[nt][1], h1, l1);
        size_t i0 = headoff + ((size_t)r0 << 10) + d0;
        *(__nv_bfloat162*)&ohi[i0] = __nv_bfloat162(h0, h1);
        *(__nv_bfloat162*)&olo[i0] = __nv_bfloat162(l0, l1);
        split1(acc[nt][2], h0, l0); split1(acc[nt][3], h1, l1);
        size_t i1 = headoff + ((size_t)(r0 + 8) << 10) + d0;
        *(__nv_bfloat162*)&ohi[i1] = __nv_bfloat162(h0, h1);
        *(__nv_bfloat162*)&olo[i1] = __nv_bfloat162(l0, l1);
    }
}

// -------------------- launch --------------------
extern "C" void kernel_launch(void* const* d_in, const int* in_sizes, int n_in,
                              void* d_out, int out_size) {
    (void)in_sizes; (void)n_in; (void)out_size;
    const float* x   = (const float*)d_in[0];
    const float* Wq  = (const float*)d_in[1];
    const float* Wk  = (const float*)d_in[2];
    const float* Wv  = (const float*)d_in[3];
    const float* gq  = (const float*)d_in[4];
    const float* gk  = (const float*)d_in[5];
    const float* Wo  = (const float*)d_in[6];
    const float* bo  = (const float*)d_in[7];
    const float* lnw = (const float*)d_in[8];
    const float* lnb = (const float*)d_in[9];
    float* out = (float*)d_out;

    float *qb, *kb, *vb, *gqv, *gkv;
    __nv_bfloat16 *xnhi, *xnlo, *xhi, *xlo, *chi, *clo, *wthi, *wtlo;
    __nv_bfloat16 *qhi, *qlo, *khi, *klo, *vthi, *vtlo;
    cudaGetSymbolAddress((void**)&qb,   g_q);
    cudaGetSymbolAddress((void**)&kb,   g_k);
    cudaGetSymbolAddress((void**)&vb,   g_v);
    cudaGetSymbolAddress((void**)&gqv,  g_gq);
    cudaGetSymbolAddress((void**)&gkv,  g_gk);
    cudaGetSymbolAddress((void**)&xnhi, g_xnhi);
    cudaGetSymbolAddress((void**)&xnlo, g_xnlo);
    cudaGetSymbolAddress((void**)&xhi,  g_xhi);
    cudaGetSymbolAddress((void**)&xlo,  g_xlo);
    cudaGetSymbolAddress((void**)&chi,  g_chi);
    cudaGetSymbolAddress((void**)&clo,  g_clo);
    cudaGetSymbolAddress((void**)&qhi,  g_qhi);
    cudaGetSymbolAddress((void**)&qlo,  g_qlo);
    cudaGetSymbolAddress((void**)&khi,  g_khi);
    cudaGetSymbolAddress((void**)&klo,  g_klo);
    cudaGetSymbolAddress((void**)&vthi, g_vthi);
    cudaGetSymbolAddress((void**)&vtlo, g_vtlo);
    cudaGetSymbolAddress((void**)&wthi, g_wthi);
    cudaGetSymbolAddress((void**)&wtlo, g_wtlo);

    const size_t WSZ = (size_t)DD * DD;

    cudaFuncSetAttribute(attn_kernel, cudaFuncAttributeMaxDynamicSharedMemorySize,
                         A_SMEM);
    cudaFuncSetAttribute(tgemm_kernel, cudaFuncAttributeMaxDynamicSharedMemorySize,
                         TG_SMEM);

    dim3 tgrid(DD / 128, MR / 128);       // (8, 32)
    dim3 wtgrid(DD / 32, DD / 32, 4);
    dim3 wtblk(32, 8);
    dim3 vtgrid(TT / 32, DD / 32, BB);

    // prep
    ln_kernel<<<MR, 256>>>(x, lnw, lnb, xnhi, xnlo);
    split_kernel<<<(MR * DD) / (256 * 4), 256>>>(x, xhi, xlo);
    wtsplit4_kernel<<<wtgrid, wtblk>>>(Wq, Wk, Wv, Wo, wthi, wtlo);

    // projections on tensor cores
    tgemm_kernel<<<tgrid, 256, TG_SMEM>>>(xnhi, xnlo, wthi + 0 * WSZ, wtlo + 0 * WSZ,
                                          nullptr, qb);
    tgemm_kernel<<<tgrid, 256, TG_SMEM>>>(xnhi, xnlo, wthi + 1 * WSZ, wtlo + 1 * WSZ,
                                          nullptr, kb);
    tgemm_kernel<<<tgrid, 256, TG_SMEM>>>(xhi,  xlo,  wthi + 2 * WSZ, wtlo + 2 * WSZ,
                                          nullptr, vb);

    qknorm_kernel<<<(MR * HH) / 8, 256>>>(qb, kb, gq, gk, qhi, qlo, khi, klo, gqv, gkv);
    vtsplit_kernel<<<vtgrid, wtblk>>>(vb, vthi, vtlo);

    attn_kernel<<<dim3(TT / 128, HH, BB), 256, A_SMEM>>>(
        qhi, qlo, khi, klo, vthi, vtlo, gqv, gkv, chi, clo);

    // output projection + bias
    tgemm_kernel<<<tgrid, 256, TG_SMEM>>>(chi, clo, wthi + 3 * WSZ, wtlo + 3 * WSZ,
                                          bo, out);
}